// round 11
// baseline (speedup 1.0000x reference)
#include <cuda_runtime.h>
#include <cuda_bf16.h>
#include <cstdint>

#define NT 49
#define CD 128

/* float-index smem offsets */
#define FB      8192      /* QKV B slab (48KB) / proj B both splits (64KB) */
#define FQb     24576     /* Q split-bf16 [4][2][64][40] */
#define FKb     34816     /* K split-bf16 [4][2][64][40] */
#define FVt     45056     /* V^T split-bf16 [4][2][32][72] */
#define F_BT    54272     /* bias table 676 f32 */
#define F_RPI   54948     /* rpi u8 [2401] */
#define F_QB    55549     /* qkv_b 384 */
#define F_PB    55933     /* proj_b 128 */
#define F_BOUNCE 24576    /* out bounce [49][132] (Qb dead) */
#define BO_LD   132
#define SMEM_BYTES (56064*4)

__device__ __align__(16) uint16_t g_qkvw[98304];  /* [slab2][split2][384][64] swizzled bf16 */
__device__ __align__(16) uint16_t g_projw[32768]; /* [split2][128][128] swizzled bf16 */

__device__ __forceinline__ uint32_t smem_u32(const void* p) {
    uint32_t a;
    asm("{ .reg .u64 t; cvta.to.shared.u64 t, %1; cvt.u32.u64 %0, t; }" : "=r"(a) : "l"(p));
    return a;
}
__device__ __forceinline__ void ldsm4(uint32_t* r, uint32_t a) {
    asm volatile("ldmatrix.sync.aligned.m8n8.x4.shared.b16 {%0,%1,%2,%3}, [%4];"
        : "=r"(r[0]), "=r"(r[1]), "=r"(r[2]), "=r"(r[3]) : "r"(a));
}
__device__ __forceinline__ void mma_bf16(float* d, const uint32_t* a, const uint32_t* b) {
    asm volatile("mma.sync.aligned.m16n8k16.row.col.f32.bf16.bf16.f32 "
        "{%0,%1,%2,%3}, {%4,%5,%6,%7}, {%8,%9}, {%0,%1,%2,%3};"
        : "+f"(d[0]), "+f"(d[1]), "+f"(d[2]), "+f"(d[3])
        : "r"(a[0]), "r"(a[1]), "r"(a[2]), "r"(a[3]), "r"(b[0]), "r"(b[1]));
}
__device__ __forceinline__ uint32_t pack_hi(float a, float b) {
    __nv_bfloat16 h0 = __float2bfloat16_rn(a), h1 = __float2bfloat16_rn(b);
    return (uint32_t)__bfloat16_as_ushort(h0) | ((uint32_t)__bfloat16_as_ushort(h1) << 16);
}
__device__ __forceinline__ uint32_t pack_lo(float a, float b) {
    __nv_bfloat16 h0 = __float2bfloat16_rn(a), h1 = __float2bfloat16_rn(b);
    float l0 = a - __bfloat162float(h0), l1 = b - __bfloat162float(h1);
    return (uint32_t)__bfloat16_as_ushort(__float2bfloat16_rn(l0)) |
           ((uint32_t)__bfloat16_as_ushort(__float2bfloat16_rn(l1)) << 16);
}

/* ---- prologue: split weights into bf16 hi/lo swizzled smem-images ---- */
__global__ void prep_w(const float* __restrict__ qkv_w, const float* __restrict__ proj_w) {
    int i = blockIdx.x * blockDim.x + threadIdx.x;
    if (i < 384 * 128) {
        int n = i >> 7, k = i & 127;
        float f = qkv_w[i];
        __nv_bfloat16 h = __float2bfloat16_rn(f);
        __nv_bfloat16 l = __float2bfloat16_rn(f - __bfloat162float(h));
        int s = k >> 6, ko = k & 63;
        int sw = (((ko >> 3) ^ (n & 7)) << 3) + (k & 7);
        g_qkvw[((s * 2 + 0) * 384 + n) * 64 + sw] = __bfloat16_as_ushort(h);
        g_qkvw[((s * 2 + 1) * 384 + n) * 64 + sw] = __bfloat16_as_ushort(l);
    }
    if (i < 128 * 128) {
        int n = i >> 7, k = i & 127;
        float f = proj_w[i];
        __nv_bfloat16 h = __float2bfloat16_rn(f);
        __nv_bfloat16 l = __float2bfloat16_rn(f - __bfloat162float(h));
        int sw = (((k >> 3) ^ (n & 7)) << 3) + (k & 7);
        g_projw[(0 * 128 + n) * 128 + sw] = __bfloat16_as_ushort(h);
        g_projw[(1 * 128 + n) * 128 + sw] = __bfloat16_as_ushort(l);
    }
}

/* ---- main fused kernel ---- */
__global__ __launch_bounds__(512, 1)
void win_attn_mma(const float* __restrict__ x,
                  const float* __restrict__ mask,
                  const float* __restrict__ qkv_b,
                  const float* __restrict__ proj_b,
                  const float* __restrict__ bt,
                  float* __restrict__ out,
                  int nW)
{
    extern __shared__ float sm[];
    uint16_t* u16b = (uint16_t*)sm;
    const int t = threadIdx.x;
    const int w = blockIdx.x;
    const long base = (long)w * (NT * CD);
    const int tn = t & 31, tm = t >> 5;
    const uint32_t smb = smem_u32(sm);

    /* ---- stage x -> A hi/lo (swizzled bf16); pads; tables; biases ---- */
    for (int idx = t; idx < NT * CD; idx += 512) {
        int r = idx >> 7, k = idx & 127;
        float f = x[base + idx];
        __nv_bfloat16 h = __float2bfloat16_rn(f);
        __nv_bfloat16 l = __float2bfloat16_rn(f - __bfloat162float(h));
        int sw = ((k >> 3) ^ (r & 7)) * 8 + (k & 7);
        u16b[r * 128 + sw]        = __bfloat16_as_ushort(h);
        u16b[(64 + r) * 128 + sw] = __bfloat16_as_ushort(l);
    }
    for (int idx = t; idx < 15 * CD; idx += 512) {
        int r = 49 + (idx >> 7), k = idx & 127;
        int sw = ((k >> 3) ^ (r & 7)) * 8 + (k & 7);
        u16b[r * 128 + sw] = 0;
        u16b[(64 + r) * 128 + sw] = 0;
    }
    if (t < 384) sm[F_QB + t] = qkv_b[t];
    if (t < 128) sm[F_PB + t] = proj_b[t];
    for (int idx = t; idx < 676; idx += 512) sm[F_BT + idx] = bt[idx];
    {   /* rpi table u8[49][49] */
        uint8_t* rpw = (uint8_t*)(sm + F_RPI);
        for (int idx = t; idx < NT * NT; idx += 512) {
            int i = idx / NT, j = idx - i * NT;
            int yi = i / 7, xi = i - yi * 7;
            int yj = j / 7, xj = j - yj * 7;
            rpw[idx] = (uint8_t)((yi - yj + 6) * 13 + (xi - xj + 6));
        }
    }
    __syncthreads();

    const int l = tn;
    const int wm = tm & 1, wn = tm >> 1;
    const int a_r_off = l & 15;
    const int a_c_off = l >> 4;
    const int b_n_off = (l & 7) + (l >> 4) * 8;
    const int b_c_off = (l >> 3) & 1;

    /* ======== QKV GEMM: D[64x384] = A[64x128] @ W^T, split-bf16 ======== */
    float dacc[2][6][4];
#pragma unroll
    for (int a = 0; a < 2; a++)
#pragma unroll
        for (int b = 0; b < 6; b++)
#pragma unroll
            for (int c = 0; c < 4; c++) dacc[a][b][c] = 0.f;

    for (int s = 0; s < 2; s++)
        for (int bsp = 0; bsp < 2; bsp++) {
            {   /* stage one split of B k-slab: [384][64] bf16 = 3072 float4 */
                const float4* src = ((const float4*)g_qkvw) + (s * 2 + bsp) * 3072;
                float4* dst = (float4*)(sm + FB);
                for (int i = t; i < 3072; i += 512) dst[i] = src[i];
            }
            __syncthreads();
#pragma unroll
            for (int kk = 0; kk < 4; kk++) {
                uint32_t afh[2][4], afl[2][4];
#pragma unroll
                for (int mt = 0; mt < 2; mt++) {
                    int r = wm * 32 + mt * 16 + a_r_off;
                    int ch = s * 8 + kk * 2 + a_c_off;
                    uint32_t ad = smb + (((r * 128) + ((ch ^ (r & 7)) << 3)) << 1);
                    ldsm4(afh[mt], ad);
                    if (bsp == 0) ldsm4(afl[mt], ad + (64 * 128 * 2));
                }
                uint32_t bf[6][2];
#pragma unroll
                for (int np = 0; np < 3; np++) {
                    int n = wn * 48 + np * 16 + b_n_off;
                    int ch = kk * 2 + b_c_off;
                    uint32_t ad = smb + FB * 4 + (((n * 64) + ((ch ^ (n & 7)) << 3)) << 1);
                    uint32_t r4[4]; ldsm4(r4, ad);
                    bf[np * 2][0] = r4[0]; bf[np * 2][1] = r4[1];
                    bf[np * 2 + 1][0] = r4[2]; bf[np * 2 + 1][1] = r4[3];
                }
#pragma unroll
                for (int mt = 0; mt < 2; mt++)
#pragma unroll
                    for (int nt = 0; nt < 6; nt++) {
                        mma_bf16(dacc[mt][nt], afh[mt], bf[nt]);
                        if (bsp == 0) mma_bf16(dacc[mt][nt], afl[mt], bf[nt]);
                    }
            }
            __syncthreads();
        }

    /* ---- QKV epilogue: fragments -> Qb (x scale) / Kb / Vt, split-bf16 ---- */
    {
        const float scale = 0.1767766952966369f;
        int r0 = wm * 32 + (l >> 2);
#pragma unroll
        for (int mt = 0; mt < 2; mt++)
#pragma unroll
            for (int nt = 0; nt < 6; nt++)
#pragma unroll
                for (int rh = 0; rh < 2; rh++) {
                    int row = r0 + mt * 16 + rh * 8;
                    if (row >= NT) continue;
                    int c = wn * 48 + nt * 8 + (l & 3) * 2;
                    float v0 = dacc[mt][nt][rh * 2]     + sm[F_QB + c];
                    float v1 = dacc[mt][nt][rh * 2 + 1] + sm[F_QB + c + 1];
                    if (c < 128) {
                        v0 *= scale; v1 *= scale;
                        int h = c >> 5, dh = c & 31;
                        int i0 = ((h * 2 + 0) * 64 + row) * 40 + dh;
                        int i1 = ((h * 2 + 1) * 64 + row) * 40 + dh;
                        *(uint32_t*)&u16b[FQb * 2 + i0] = pack_hi(v0, v1);
                        *(uint32_t*)&u16b[FQb * 2 + i1] = pack_lo(v0, v1);
                    } else if (c < 256) {
                        int h = (c - 128) >> 5, dh = (c - 128) & 31;
                        int i0 = ((h * 2 + 0) * 64 + row) * 40 + dh;
                        int i1 = ((h * 2 + 1) * 64 + row) * 40 + dh;
                        *(uint32_t*)&u16b[FKb * 2 + i0] = pack_hi(v0, v1);
                        *(uint32_t*)&u16b[FKb * 2 + i1] = pack_lo(v0, v1);
                    } else {
                        int h = (c - 256) >> 5, dh = (c - 256) & 31;
                        __nv_bfloat16 h0 = __float2bfloat16_rn(v0);
                        __nv_bfloat16 h1 = __float2bfloat16_rn(v1);
                        __nv_bfloat16 l0 = __float2bfloat16_rn(v0 - __bfloat162float(h0));
                        __nv_bfloat16 l1 = __float2bfloat16_rn(v1 - __bfloat162float(h1));
                        int bh = FVt * 2 + ((h * 2 + 0) * 32 + dh) * 72 + row;
                        int bl = FVt * 2 + ((h * 2 + 1) * 32 + dh) * 72 + row;
                        u16b[bh]      = __bfloat16_as_ushort(h0);
                        u16b[bh + 72] = __bfloat16_as_ushort(h1);
                        u16b[bl]      = __bfloat16_as_ushort(l0);
                        u16b[bl + 72] = __bfloat16_as_ushort(l1);
                    }
                }
    }
    /* zero Vt key-pad cols 49..63 (0*garbage != NaN safety) */
    for (int i = t; i < 8 * 32 * 15; i += 512) {
        int hs = i / (32 * 15), rem = i - hs * (32 * 15);
        int dh = rem / 15, jj = rem - dh * 15;
        u16b[FVt * 2 + (hs * 32 + dh) * 72 + 49 + jj] = 0;
    }
    /* stage proj B now (both splits, 4096 float4) — latency hides behind attention */
    {
        const float4* src = (const float4*)g_projw;
        float4* dst = (float4*)(sm + FB);
        for (int i = t; i < 4096; i += 512) dst[i] = src[i];
    }
    __syncthreads();

    /* ======== attention, fully register-resident: 16 warps = 4 heads x 4 m-tiles ======== */
    const float* mrow = mask + (long)(w % nW) * (NT * NT);
    const uint8_t* rp = (const uint8_t*)(sm + F_RPI);
    const int h = tm >> 2, amt = tm & 3;
    const int cbase = (l & 3) * 2;
    const int r0 = amt * 16 + (l >> 2);
    const int r1 = r0 + 8;

    /* ---- S = (Q*scale) K^T : m16 x n64 per warp ---- */
    float sacc[8][4];
#pragma unroll
    for (int a = 0; a < 8; a++)
#pragma unroll
        for (int c = 0; c < 4; c++) sacc[a][c] = 0.f;

#pragma unroll
    for (int kk = 0; kk < 2; kk++) {
        uint32_t aq[2][4];
#pragma unroll
        for (int sp = 0; sp < 2; sp++)
            ldsm4(aq[sp], smb + FQb * 4 +
                ((((h * 2 + sp) * 64 + amt * 16 + a_r_off) * 40 + (kk * 2 + a_c_off) * 8) << 1));
        uint32_t bk[8][2][2];
#pragma unroll
        for (int g = 0; g < 4; g++)
#pragma unroll
            for (int sp = 0; sp < 2; sp++) {
                uint32_t r4[4];
                ldsm4(r4, smb + FKb * 4 +
                    ((((h * 2 + sp) * 64 + g * 16 + b_n_off) * 40 + (kk * 2 + b_c_off) * 8) << 1));
                bk[g * 2][sp][0] = r4[0]; bk[g * 2][sp][1] = r4[1];
                bk[g * 2 + 1][sp][0] = r4[2]; bk[g * 2 + 1][sp][1] = r4[3];
            }
#pragma unroll
        for (int nt = 0; nt < 8; nt++) {
            mma_bf16(sacc[nt], aq[0], bk[nt][0]);
            mma_bf16(sacc[nt], aq[0], bk[nt][1]);
            mma_bf16(sacc[nt], aq[1], bk[nt][0]);
        }
    }

    /* ---- softmax in registers (+bias+mask); rows reduce over 4 lanes ---- */
    {
        int r0c = (r0 < NT) ? r0 : (NT - 1);
        int r1c = (r1 < NT) ? r1 : (NT - 1);
        float m0 = -1e30f, m1 = -1e30f;
#pragma unroll
        for (int nt = 0; nt < 8; nt++)
#pragma unroll
            for (int j = 0; j < 2; j++) {
                int c = nt * 8 + cbase + j;
                if (c < NT) {
                    float bi0 = sm[F_BT + rp[r0c * NT + c] * 4 + h];
                    float bi1 = sm[F_BT + rp[r1c * NT + c] * 4 + h];
                    float mk0 = (r0 < NT) ? mrow[r0 * NT + c] : 0.f;
                    float mk1 = (r1 < NT) ? mrow[r1 * NT + c] : 0.f;
                    sacc[nt][j]     += bi0 + mk0;
                    sacc[nt][2 + j] += bi1 + mk1;
                } else {
                    sacc[nt][j] = -1e30f;
                    sacc[nt][2 + j] = -1e30f;
                }
                m0 = fmaxf(m0, sacc[nt][j]);
                m1 = fmaxf(m1, sacc[nt][2 + j]);
            }
        m0 = fmaxf(m0, __shfl_xor_sync(0xffffffffu, m0, 1));
        m0 = fmaxf(m0, __shfl_xor_sync(0xffffffffu, m0, 2));
        m1 = fmaxf(m1, __shfl_xor_sync(0xffffffffu, m1, 1));
        m1 = fmaxf(m1, __shfl_xor_sync(0xffffffffu, m1, 2));
        float s0 = 0.f, s1 = 0.f;
#pragma unroll
        for (int nt = 0; nt < 8; nt++)
#pragma unroll
            for (int j = 0; j < 2; j++) {
                float e0 = __expf(sacc[nt][j] - m0);
                float e1 = __expf(sacc[nt][2 + j] - m1);
                sacc[nt][j] = e0; sacc[nt][2 + j] = e1;
                s0 += e0; s1 += e1;
            }
        s0 += __shfl_xor_sync(0xffffffffu, s0, 1);
        s0 += __shfl_xor_sync(0xffffffffu, s0, 2);
        s1 += __shfl_xor_sync(0xffffffffu, s1, 1);
        s1 += __shfl_xor_sync(0xffffffffu, s1, 2);
        float i0 = 1.f / s0, i1 = 1.f / s1;
#pragma unroll
        for (int nt = 0; nt < 8; nt++)
#pragma unroll
            for (int j = 0; j < 2; j++) { sacc[nt][j] *= i0; sacc[nt][2 + j] *= i1; }
    }

    /* ---- O = P V : P fragments straight from registers (D-layout == A-layout) ---- */
    float oacc[4][4];
#pragma unroll
    for (int a = 0; a < 4; a++)
#pragma unroll
        for (int c = 0; c < 4; c++) oacc[a][c] = 0.f;

#pragma unroll
    for (int kt = 0; kt < 4; kt++) {
        uint32_t ah[4], al[4];
        ah[0] = pack_hi(sacc[2 * kt][0], sacc[2 * kt][1]);
        ah[1] = pack_hi(sacc[2 * kt][2], sacc[2 * kt][3]);
        ah[2] = pack_hi(sacc[2 * kt + 1][0], sacc[2 * kt + 1][1]);
        ah[3] = pack_hi(sacc[2 * kt + 1][2], sacc[2 * kt + 1][3]);
        al[0] = pack_lo(sacc[2 * kt][0], sacc[2 * kt][1]);
        al[1] = pack_lo(sacc[2 * kt][2], sacc[2 * kt][3]);
        al[2] = pack_lo(sacc[2 * kt + 1][0], sacc[2 * kt + 1][1]);
        al[3] = pack_lo(sacc[2 * kt + 1][2], sacc[2 * kt + 1][3]);
        uint32_t bv[4][2][2];
#pragma unroll
        for (int g = 0; g < 2; g++)
#pragma unroll
            for (int sp = 0; sp < 2; sp++) {
                uint32_t r4[4];
                ldsm4(r4, smb + FVt * 4 +
                    ((((h * 2 + sp) * 32 + g * 16 + b_n_off) * 72 + kt * 16 + b_c_off * 8) << 1));
                bv[g * 2][sp][0] = r4[0]; bv[g * 2][sp][1] = r4[1];
                bv[g * 2 + 1][sp][0] = r4[2]; bv[g * 2 + 1][sp][1] = r4[3];
            }
#pragma unroll
        for (int n = 0; n < 4; n++) {
            mma_bf16(oacc[n], ah, bv[n][0]);
            mma_bf16(oacc[n], ah, bv[n][1]);
            mma_bf16(oacc[n], al, bv[n][0]);
        }
    }

    /* ---- O fragments -> proj-A split-bf16 swizzled (region 0) ---- */
#pragma unroll
    for (int n = 0; n < 4; n++)
#pragma unroll
        for (int rh = 0; rh < 2; rh++) {
            int row = amt * 16 + (l >> 2) + rh * 8;
            int c = h * 32 + n * 8 + cbase;
            float v0 = oacc[n][rh * 2], v1 = oacc[n][rh * 2 + 1];
            int sw = (((c >> 3) ^ (row & 7)) << 3) + (c & 7);
            *(uint32_t*)&u16b[row * 128 + sw]        = pack_hi(v0, v1);
            *(uint32_t*)&u16b[(64 + row) * 128 + sw] = pack_lo(v0, v1);
        }
    __syncthreads();

    /* ======== proj GEMM: D[64x128] = O @ proj_w^T, split-bf16 ======== */
    float pacc[2][2][4];
#pragma unroll
    for (int a = 0; a < 2; a++)
#pragma unroll
        for (int b = 0; b < 2; b++)
#pragma unroll
            for (int c = 0; c < 4; c++) pacc[a][b][c] = 0.f;

#pragma unroll
    for (int kk = 0; kk < 8; kk++) {
        uint32_t af[2][2][4];
#pragma unroll
        for (int mt2 = 0; mt2 < 2; mt2++)
#pragma unroll
            for (int sp = 0; sp < 2; sp++) {
                int r = wm * 32 + mt2 * 16 + a_r_off;
                int ch = kk * 2 + a_c_off;
                uint32_t ad = smb + ((((sp * 64 + r) * 128) + ((ch ^ (r & 7)) << 3)) << 1);
                ldsm4(af[mt2][sp], ad);
            }
        uint32_t bf2[2][2][2];
#pragma unroll
        for (int sp = 0; sp < 2; sp++) {
            int n = wn * 16 + b_n_off;
            int ch = kk * 2 + b_c_off;
            uint32_t ad = smb + FB * 4 + ((((sp * 128 + n) * 128) + ((ch ^ (n & 7)) << 3)) << 1);
            uint32_t r4[4]; ldsm4(r4, ad);
            bf2[0][sp][0] = r4[0]; bf2[0][sp][1] = r4[1];
            bf2[1][sp][0] = r4[2]; bf2[1][sp][1] = r4[3];
        }
#pragma unroll
        for (int mt2 = 0; mt2 < 2; mt2++)
#pragma unroll
            for (int nt = 0; nt < 2; nt++) {
                mma_bf16(pacc[mt2][nt], af[mt2][0], bf2[nt][0]);
                mma_bf16(pacc[mt2][nt], af[mt2][0], bf2[nt][1]);
                mma_bf16(pacc[mt2][nt], af[mt2][1], bf2[nt][0]);
            }
    }
    __syncthreads();

    /* ---- proj epilogue: accum+bias -> bounce -> coalesced store ---- */
    {
        int r0p = wm * 32 + (l >> 2);
#pragma unroll
        for (int mt2 = 0; mt2 < 2; mt2++)
#pragma unroll
            for (int nt = 0; nt < 2; nt++)
#pragma unroll
                for (int rg = 0; rg < 4; rg++) {
                    int row = r0p + mt2 * 16 + ((rg >> 1) << 3);
                    int col = wn * 16 + nt * 8 + (l & 3) * 2 + (rg & 1);
                    if (row < NT)
                        sm[F_BOUNCE + row * BO_LD + col] = pacc[mt2][nt][rg] + sm[F_PB + col];
                }
    }
    __syncthreads();
    for (int idx = t; idx < NT * CD; idx += 512)
        out[base + idx] = sm[F_BOUNCE + (idx >> 7) * BO_LD + (idx & 127)];
}

extern "C" void kernel_launch(void* const* d_in, const int* in_sizes, int n_in,
                              void* d_out, int out_size) {
    const float* x      = (const float*)d_in[0];
    const float* mask   = (const float*)d_in[1];
    const float* qkv_w  = (const float*)d_in[2];
    const float* qkv_b  = (const float*)d_in[3];
    const float* proj_w = (const float*)d_in[4];
    const float* proj_b = (const float*)d_in[5];
    const float* bt     = (const float*)d_in[6];
    float* out = (float*)d_out;

    int B  = in_sizes[0] / (NT * CD);     /* 16384 */
    int nW = in_sizes[1] / (NT * NT);     /* 1024 */

    prep_w<<<96, 512>>>(qkv_w, proj_w);

    cudaFuncSetAttribute(win_attn_mma,
                         cudaFuncAttributeMaxDynamicSharedMemorySize, SMEM_BYTES);
    win_attn_mma<<<B, 512, SMEM_BYTES>>>(x, mask, qkv_b, proj_b, bt, out, nW);
}

// round 12
// speedup vs baseline: 1.0064x; 1.0064x over previous
#include <cuda_runtime.h>
#include <cuda_bf16.h>
#include <cstdint>

#define NT 49
#define CD 128

/* float-index smem offsets */
#define FB      8192      /* QKV B slab (48KB) / proj B both splits (64KB) */
#define FQb     24576     /* Q split-bf16 [4][2][64][40] */
#define FKb     34816     /* K split-bf16 [4][2][64][40] */
#define FVt     45056     /* V^T split-bf16 [4][2][32][72] */
#define F_BT    54272     /* bias table 676 f32 */
#define F_RPI   54948     /* rpi u8 [2401] */
#define F_QB    55549     /* qkv_b 384 */
#define F_PB    55933     /* proj_b 128 */
#define F_BOUNCE 24576    /* out bounce [49][132] (Qb dead) */
#define BO_LD   132
#define SMEM_BYTES (56064*4)

__device__ __align__(16) uint16_t g_qkvw[98304];  /* [slab2][split2][384][64] swizzled bf16 */
__device__ __align__(16) uint16_t g_projw[32768]; /* [split2][128][128] swizzled bf16 */

__device__ __forceinline__ uint32_t smem_u32(const void* p) {
    uint32_t a;
    asm("{ .reg .u64 t; cvta.to.shared.u64 t, %1; cvt.u32.u64 %0, t; }" : "=r"(a) : "l"(p));
    return a;
}
__device__ __forceinline__ void ldsm4(uint32_t* r, uint32_t a) {
    asm volatile("ldmatrix.sync.aligned.m8n8.x4.shared.b16 {%0,%1,%2,%3}, [%4];"
        : "=r"(r[0]), "=r"(r[1]), "=r"(r[2]), "=r"(r[3]) : "r"(a));
}
__device__ __forceinline__ void mma_bf16(float* d, const uint32_t* a, const uint32_t* b) {
    asm volatile("mma.sync.aligned.m16n8k16.row.col.f32.bf16.bf16.f32 "
        "{%0,%1,%2,%3}, {%4,%5,%6,%7}, {%8,%9}, {%0,%1,%2,%3};"
        : "+f"(d[0]), "+f"(d[1]), "+f"(d[2]), "+f"(d[3])
        : "r"(a[0]), "r"(a[1]), "r"(a[2]), "r"(a[3]), "r"(b[0]), "r"(b[1]));
}
__device__ __forceinline__ uint32_t pack_hi(float a, float b) {
    __nv_bfloat16 h0 = __float2bfloat16_rn(a), h1 = __float2bfloat16_rn(b);
    return (uint32_t)__bfloat16_as_ushort(h0) | ((uint32_t)__bfloat16_as_ushort(h1) << 16);
}
__device__ __forceinline__ uint32_t pack_lo(float a, float b) {
    __nv_bfloat16 h0 = __float2bfloat16_rn(a), h1 = __float2bfloat16_rn(b);
    float l0 = a - __bfloat162float(h0), l1 = b - __bfloat162float(h1);
    return (uint32_t)__bfloat16_as_ushort(__float2bfloat16_rn(l0)) |
           ((uint32_t)__bfloat16_as_ushort(__float2bfloat16_rn(l1)) << 16);
}

/* ---- prologue: split weights into bf16 hi/lo swizzled smem-images ---- */
__global__ void prep_w(const float* __restrict__ qkv_w, const float* __restrict__ proj_w) {
    int i = blockIdx.x * blockDim.x + threadIdx.x;
    if (i < 384 * 128) {
        int n = i >> 7, k = i & 127;
        float f = qkv_w[i];
        __nv_bfloat16 h = __float2bfloat16_rn(f);
        __nv_bfloat16 l = __float2bfloat16_rn(f - __bfloat162float(h));
        int s = k >> 6, ko = k & 63;
        int sw = (((ko >> 3) ^ (n & 7)) << 3) + (k & 7);
        g_qkvw[((s * 2 + 0) * 384 + n) * 64 + sw] = __bfloat16_as_ushort(h);
        g_qkvw[((s * 2 + 1) * 384 + n) * 64 + sw] = __bfloat16_as_ushort(l);
    }
    if (i < 128 * 128) {
        int n = i >> 7, k = i & 127;
        float f = proj_w[i];
        __nv_bfloat16 h = __float2bfloat16_rn(f);
        __nv_bfloat16 l = __float2bfloat16_rn(f - __bfloat162float(h));
        int sw = (((k >> 3) ^ (n & 7)) << 3) + (k & 7);
        g_projw[(0 * 128 + n) * 128 + sw] = __bfloat16_as_ushort(h);
        g_projw[(1 * 128 + n) * 128 + sw] = __bfloat16_as_ushort(l);
    }
}

/* ---- main fused kernel ---- */
__global__ __launch_bounds__(512, 1)
void win_attn_mma(const float* __restrict__ x,
                  const float* __restrict__ mask,
                  const float* __restrict__ qkv_b,
                  const float* __restrict__ proj_b,
                  const float* __restrict__ bt,
                  float* __restrict__ out,
                  int nW)
{
    extern __shared__ float sm[];
    uint16_t* u16b = (uint16_t*)sm;
    const int t = threadIdx.x;
    const int w = blockIdx.x;
    const long base = (long)w * (NT * CD);
    const int tn = t & 31, tm = t >> 5;
    const uint32_t smb = smem_u32(sm);

    /* ---- stage x -> A hi/lo (swizzled bf16); pads; tables; biases ---- */
    for (int idx = t; idx < NT * CD; idx += 512) {
        int r = idx >> 7, k = idx & 127;
        float f = x[base + idx];
        __nv_bfloat16 h = __float2bfloat16_rn(f);
        __nv_bfloat16 l = __float2bfloat16_rn(f - __bfloat162float(h));
        int sw = ((k >> 3) ^ (r & 7)) * 8 + (k & 7);
        u16b[r * 128 + sw]        = __bfloat16_as_ushort(h);
        u16b[(64 + r) * 128 + sw] = __bfloat16_as_ushort(l);
    }
    for (int idx = t; idx < 15 * CD; idx += 512) {
        int r = 49 + (idx >> 7), k = idx & 127;
        int sw = ((k >> 3) ^ (r & 7)) * 8 + (k & 7);
        u16b[r * 128 + sw] = 0;
        u16b[(64 + r) * 128 + sw] = 0;
    }
    if (t < 384) sm[F_QB + t] = qkv_b[t];
    if (t < 128) sm[F_PB + t] = proj_b[t];
    for (int idx = t; idx < 676; idx += 512) sm[F_BT + idx] = bt[idx];
    {   /* rpi table u8[49][49] */
        uint8_t* rpw = (uint8_t*)(sm + F_RPI);
        for (int idx = t; idx < NT * NT; idx += 512) {
            int i = idx / NT, j = idx - i * NT;
            int yi = i / 7, xi = i - yi * 7;
            int yj = j / 7, xj = j - yj * 7;
            rpw[idx] = (uint8_t)((yi - yj + 6) * 13 + (xi - xj + 6));
        }
    }
    __syncthreads();

    const int l = tn;
    const int wm = tm & 1, wn = tm >> 1;
    const int a_r_off = l & 15;
    const int a_c_off = l >> 4;
    const int b_n_off = (l & 7) + (l >> 4) * 8;
    const int b_c_off = (l >> 3) & 1;

    /* ======== QKV GEMM: D[64x384] = A[64x128] @ W^T, split-bf16 ======== */
    float dacc[2][6][4];
#pragma unroll
    for (int a = 0; a < 2; a++)
#pragma unroll
        for (int b = 0; b < 6; b++)
#pragma unroll
            for (int c = 0; c < 4; c++) dacc[a][b][c] = 0.f;

    for (int s = 0; s < 2; s++)
        for (int bsp = 0; bsp < 2; bsp++) {
            {   /* stage one split of B k-slab: [384][64] bf16 = 3072 float4 */
                const float4* src = ((const float4*)g_qkvw) + (s * 2 + bsp) * 3072;
                float4* dst = (float4*)(sm + FB);
                for (int i = t; i < 3072; i += 512) dst[i] = src[i];
            }
            __syncthreads();
#pragma unroll
            for (int kk = 0; kk < 4; kk++) {
                uint32_t afh[2][4], afl[2][4];
#pragma unroll
                for (int mt = 0; mt < 2; mt++) {
                    int r = wm * 32 + mt * 16 + a_r_off;
                    int ch = s * 8 + kk * 2 + a_c_off;
                    uint32_t ad = smb + (((r * 128) + ((ch ^ (r & 7)) << 3)) << 1);
                    ldsm4(afh[mt], ad);
                    if (bsp == 0) ldsm4(afl[mt], ad + (64 * 128 * 2));
                }
                uint32_t bf[6][2];
#pragma unroll
                for (int np = 0; np < 3; np++) {
                    int n = wn * 48 + np * 16 + b_n_off;
                    int ch = kk * 2 + b_c_off;
                    uint32_t ad = smb + FB * 4 + (((n * 64) + ((ch ^ (n & 7)) << 3)) << 1);
                    uint32_t r4[4]; ldsm4(r4, ad);
                    bf[np * 2][0] = r4[0]; bf[np * 2][1] = r4[1];
                    bf[np * 2 + 1][0] = r4[2]; bf[np * 2 + 1][1] = r4[3];
                }
#pragma unroll
                for (int mt = 0; mt < 2; mt++)
#pragma unroll
                    for (int nt = 0; nt < 6; nt++) {
                        mma_bf16(dacc[mt][nt], afh[mt], bf[nt]);
                        if (bsp == 0) mma_bf16(dacc[mt][nt], afl[mt], bf[nt]);
                    }
            }
            __syncthreads();
        }

    /* ---- QKV epilogue: fragments -> Qb (x scale) / Kb / Vt, split-bf16 ---- */
    {
        const float scale = 0.1767766952966369f;
        int r0 = wm * 32 + (l >> 2);
#pragma unroll
        for (int mt = 0; mt < 2; mt++)
#pragma unroll
            for (int nt = 0; nt < 6; nt++)
#pragma unroll
                for (int rh = 0; rh < 2; rh++) {
                    int row = r0 + mt * 16 + rh * 8;
                    if (row >= NT) continue;
                    int c = wn * 48 + nt * 8 + (l & 3) * 2;
                    float v0 = dacc[mt][nt][rh * 2]     + sm[F_QB + c];
                    float v1 = dacc[mt][nt][rh * 2 + 1] + sm[F_QB + c + 1];
                    if (c < 128) {
                        v0 *= scale; v1 *= scale;
                        int h = c >> 5, dh = c & 31;
                        int i0 = ((h * 2 + 0) * 64 + row) * 40 + dh;
                        int i1 = ((h * 2 + 1) * 64 + row) * 40 + dh;
                        *(uint32_t*)&u16b[FQb * 2 + i0] = pack_hi(v0, v1);
                        *(uint32_t*)&u16b[FQb * 2 + i1] = pack_lo(v0, v1);
                    } else if (c < 256) {
                        int h = (c - 128) >> 5, dh = (c - 128) & 31;
                        int i0 = ((h * 2 + 0) * 64 + row) * 40 + dh;
                        int i1 = ((h * 2 + 1) * 64 + row) * 40 + dh;
                        *(uint32_t*)&u16b[FKb * 2 + i0] = pack_hi(v0, v1);
                        *(uint32_t*)&u16b[FKb * 2 + i1] = pack_lo(v0, v1);
                    } else {
                        int h = (c - 256) >> 5, dh = (c - 256) & 31;
                        __nv_bfloat16 h0 = __float2bfloat16_rn(v0);
                        __nv_bfloat16 h1 = __float2bfloat16_rn(v1);
                        __nv_bfloat16 l0 = __float2bfloat16_rn(v0 - __bfloat162float(h0));
                        __nv_bfloat16 l1 = __float2bfloat16_rn(v1 - __bfloat162float(h1));
                        int bh = FVt * 2 + ((h * 2 + 0) * 32 + dh) * 72 + row;
                        int bl = FVt * 2 + ((h * 2 + 1) * 32 + dh) * 72 + row;
                        u16b[bh]      = __bfloat16_as_ushort(h0);
                        u16b[bh + 72] = __bfloat16_as_ushort(h1);
                        u16b[bl]      = __bfloat16_as_ushort(l0);
                        u16b[bl + 72] = __bfloat16_as_ushort(l1);
                    }
                }
    }
    /* zero Vt key-pad cols 49..63 (0*garbage != NaN safety) */
    for (int i = t; i < 8 * 32 * 15; i += 512) {
        int hs = i / (32 * 15), rem = i - hs * (32 * 15);
        int dh = rem / 15, jj = rem - dh * 15;
        u16b[FVt * 2 + (hs * 32 + dh) * 72 + 49 + jj] = 0;
    }
    /* stage proj B now (both splits, 4096 float4) — latency hides behind attention */
    {
        const float4* src = (const float4*)g_projw;
        float4* dst = (float4*)(sm + FB);
        for (int i = t; i < 4096; i += 512) dst[i] = src[i];
    }
    __syncthreads();

    /* ======== attention, fully register-resident: 16 warps = 4 heads x 4 m-tiles ======== */
    const float* mrow = mask + (long)(w % nW) * (NT * NT);
    const uint8_t* rp = (const uint8_t*)(sm + F_RPI);
    const int h = tm >> 2, amt = tm & 3;
    const int cbase = (l & 3) * 2;
    const int r0 = amt * 16 + (l >> 2);
    const int r1 = r0 + 8;

    /* ---- S = (Q*scale) K^T : m16 x n64 per warp ---- */
    float sacc[8][4];
#pragma unroll
    for (int a = 0; a < 8; a++)
#pragma unroll
        for (int c = 0; c < 4; c++) sacc[a][c] = 0.f;

#pragma unroll
    for (int kk = 0; kk < 2; kk++) {
        uint32_t aq[2][4];
#pragma unroll
        for (int sp = 0; sp < 2; sp++)
            ldsm4(aq[sp], smb + FQb * 4 +
                ((((h * 2 + sp) * 64 + amt * 16 + a_r_off) * 40 + (kk * 2 + a_c_off) * 8) << 1));
        uint32_t bk[8][2][2];
#pragma unroll
        for (int g = 0; g < 4; g++)
#pragma unroll
            for (int sp = 0; sp < 2; sp++) {
                uint32_t r4[4];
                ldsm4(r4, smb + FKb * 4 +
                    ((((h * 2 + sp) * 64 + g * 16 + b_n_off) * 40 + (kk * 2 + b_c_off) * 8) << 1));
                bk[g * 2][sp][0] = r4[0]; bk[g * 2][sp][1] = r4[1];
                bk[g * 2 + 1][sp][0] = r4[2]; bk[g * 2 + 1][sp][1] = r4[3];
            }
#pragma unroll
        for (int nt = 0; nt < 8; nt++) {
            mma_bf16(sacc[nt], aq[0], bk[nt][0]);
            mma_bf16(sacc[nt], aq[0], bk[nt][1]);
            mma_bf16(sacc[nt], aq[1], bk[nt][0]);
        }
    }

    /* ---- softmax in registers (+bias+mask); rows reduce over 4 lanes ---- */
    {
        int r0c = (r0 < NT) ? r0 : (NT - 1);
        int r1c = (r1 < NT) ? r1 : (NT - 1);
        float m0 = -1e30f, m1 = -1e30f;
#pragma unroll
        for (int nt = 0; nt < 8; nt++)
#pragma unroll
            for (int j = 0; j < 2; j++) {
                int c = nt * 8 + cbase + j;
                if (c < NT) {
                    float bi0 = sm[F_BT + rp[r0c * NT + c] * 4 + h];
                    float bi1 = sm[F_BT + rp[r1c * NT + c] * 4 + h];
                    float mk0 = (r0 < NT) ? mrow[r0 * NT + c] : 0.f;
                    float mk1 = (r1 < NT) ? mrow[r1 * NT + c] : 0.f;
                    sacc[nt][j]     += bi0 + mk0;
                    sacc[nt][2 + j] += bi1 + mk1;
                } else {
                    sacc[nt][j] = -1e30f;
                    sacc[nt][2 + j] = -1e30f;
                }
                m0 = fmaxf(m0, sacc[nt][j]);
                m1 = fmaxf(m1, sacc[nt][2 + j]);
            }
        m0 = fmaxf(m0, __shfl_xor_sync(0xffffffffu, m0, 1));
        m0 = fmaxf(m0, __shfl_xor_sync(0xffffffffu, m0, 2));
        m1 = fmaxf(m1, __shfl_xor_sync(0xffffffffu, m1, 1));
        m1 = fmaxf(m1, __shfl_xor_sync(0xffffffffu, m1, 2));
        float s0 = 0.f, s1 = 0.f;
#pragma unroll
        for (int nt = 0; nt < 8; nt++)
#pragma unroll
            for (int j = 0; j < 2; j++) {
                float e0 = __expf(sacc[nt][j] - m0);
                float e1 = __expf(sacc[nt][2 + j] - m1);
                sacc[nt][j] = e0; sacc[nt][2 + j] = e1;
                s0 += e0; s1 += e1;
            }
        s0 += __shfl_xor_sync(0xffffffffu, s0, 1);
        s0 += __shfl_xor_sync(0xffffffffu, s0, 2);
        s1 += __shfl_xor_sync(0xffffffffu, s1, 1);
        s1 += __shfl_xor_sync(0xffffffffu, s1, 2);
        float i0 = 1.f / s0, i1 = 1.f / s1;
#pragma unroll
        for (int nt = 0; nt < 8; nt++)
#pragma unroll
            for (int j = 0; j < 2; j++) { sacc[nt][j] *= i0; sacc[nt][2 + j] *= i1; }
    }

    /* ---- O = P V : P fragments straight from registers (D-layout == A-layout) ---- */
    float oacc[4][4];
#pragma unroll
    for (int a = 0; a < 4; a++)
#pragma unroll
        for (int c = 0; c < 4; c++) oacc[a][c] = 0.f;

#pragma unroll
    for (int kt = 0; kt < 4; kt++) {
        uint32_t ah[4], al[4];
        ah[0] = pack_hi(sacc[2 * kt][0], sacc[2 * kt][1]);
        ah[1] = pack_hi(sacc[2 * kt][2], sacc[2 * kt][3]);
        ah[2] = pack_hi(sacc[2 * kt + 1][0], sacc[2 * kt + 1][1]);
        ah[3] = pack_hi(sacc[2 * kt + 1][2], sacc[2 * kt + 1][3]);
        al[0] = pack_lo(sacc[2 * kt][0], sacc[2 * kt][1]);
        al[1] = pack_lo(sacc[2 * kt][2], sacc[2 * kt][3]);
        al[2] = pack_lo(sacc[2 * kt + 1][0], sacc[2 * kt + 1][1]);
        al[3] = pack_lo(sacc[2 * kt + 1][2], sacc[2 * kt + 1][3]);
        uint32_t bv[4][2][2];
#pragma unroll
        for (int g = 0; g < 2; g++)
#pragma unroll
            for (int sp = 0; sp < 2; sp++) {
                uint32_t r4[4];
                ldsm4(r4, smb + FVt * 4 +
                    ((((h * 2 + sp) * 32 + g * 16 + b_n_off) * 72 + kt * 16 + b_c_off * 8) << 1));
                bv[g * 2][sp][0] = r4[0]; bv[g * 2][sp][1] = r4[1];
                bv[g * 2 + 1][sp][0] = r4[2]; bv[g * 2 + 1][sp][1] = r4[3];
            }
#pragma unroll
        for (int n = 0; n < 4; n++) {
            mma_bf16(oacc[n], ah, bv[n][0]);
            mma_bf16(oacc[n], ah, bv[n][1]);
            mma_bf16(oacc[n], al, bv[n][0]);
        }
    }

    /* ---- O fragments -> proj-A split-bf16 swizzled (region 0) ---- */
#pragma unroll
    for (int n = 0; n < 4; n++)
#pragma unroll
        for (int rh = 0; rh < 2; rh++) {
            int row = amt * 16 + (l >> 2) + rh * 8;
            int c = h * 32 + n * 8 + cbase;
            float v0 = oacc[n][rh * 2], v1 = oacc[n][rh * 2 + 1];
            int sw = (((c >> 3) ^ (row & 7)) << 3) + (c & 7);
            *(uint32_t*)&u16b[row * 128 + sw]        = pack_hi(v0, v1);
            *(uint32_t*)&u16b[(64 + row) * 128 + sw] = pack_lo(v0, v1);
        }
    __syncthreads();

    /* ======== proj GEMM: D[64x128] = O @ proj_w^T, split-bf16 ======== */
    float pacc[2][2][4];
#pragma unroll
    for (int a = 0; a < 2; a++)
#pragma unroll
        for (int b = 0; b < 2; b++)
#pragma unroll
            for (int c = 0; c < 4; c++) pacc[a][b][c] = 0.f;

#pragma unroll
    for (int kk = 0; kk < 8; kk++) {
        uint32_t af[2][2][4];
#pragma unroll
        for (int mt2 = 0; mt2 < 2; mt2++)
#pragma unroll
            for (int sp = 0; sp < 2; sp++) {
                int r = wm * 32 + mt2 * 16 + a_r_off;
                int ch = kk * 2 + a_c_off;
                uint32_t ad = smb + ((((sp * 64 + r) * 128) + ((ch ^ (r & 7)) << 3)) << 1);
                ldsm4(af[mt2][sp], ad);
            }
        uint32_t bf2[2][2][2];
#pragma unroll
        for (int sp = 0; sp < 2; sp++) {
            int n = wn * 16 + b_n_off;
            int ch = kk * 2 + b_c_off;
            uint32_t ad = smb + FB * 4 + ((((sp * 128 + n) * 128) + ((ch ^ (n & 7)) << 3)) << 1);
            uint32_t r4[4]; ldsm4(r4, ad);
            bf2[0][sp][0] = r4[0]; bf2[0][sp][1] = r4[1];
            bf2[1][sp][0] = r4[2]; bf2[1][sp][1] = r4[3];
        }
#pragma unroll
        for (int mt2 = 0; mt2 < 2; mt2++)
#pragma unroll
            for (int nt = 0; nt < 2; nt++) {
                mma_bf16(pacc[mt2][nt], af[mt2][0], bf2[nt][0]);
                mma_bf16(pacc[mt2][nt], af[mt2][0], bf2[nt][1]);
                mma_bf16(pacc[mt2][nt], af[mt2][1], bf2[nt][0]);
            }
    }
    __syncthreads();

    /* ---- proj epilogue: accum+bias -> bounce -> coalesced store ---- */
    {
        int r0p = wm * 32 + (l >> 2);
#pragma unroll
        for (int mt2 = 0; mt2 < 2; mt2++)
#pragma unroll
            for (int nt = 0; nt < 2; nt++)
#pragma unroll
                for (int rg = 0; rg < 4; rg++) {
                    int row = r0p + mt2 * 16 + ((rg >> 1) << 3);
                    int col = wn * 16 + nt * 8 + (l & 3) * 2 + (rg & 1);
                    if (row < NT)
                        sm[F_BOUNCE + row * BO_LD + col] = pacc[mt2][nt][rg] + sm[F_PB + col];
                }
    }
    __syncthreads();
    for (int idx = t; idx < NT * CD; idx += 512)
        out[base + idx] = sm[F_BOUNCE + (idx >> 7) * BO_LD + (idx & 127)];
}

extern "C" void kernel_launch(void* const* d_in, const int* in_sizes, int n_in,
                              void* d_out, int out_size) {
    const float* x      = (const float*)d_in[0];
    const float* mask   = (const float*)d_in[1];
    const float* qkv_w  = (const float*)d_in[2];
    const float* qkv_b  = (const float*)d_in[3];
    const float* proj_w = (const float*)d_in[4];
    const float* proj_b = (const float*)d_in[5];
    const float* bt     = (const float*)d_in[6];
    float* out = (float*)d_out;

    int B  = in_sizes[0] / (NT * CD);     /* 16384 */
    int nW = in_sizes[1] / (NT * NT);     /* 1024 */

    prep_w<<<96, 512>>>(qkv_w, proj_w);

    cudaFuncSetAttribute(win_attn_mma,
                         cudaFuncAttributeMaxDynamicSharedMemorySize, SMEM_BYTES);
    win_attn_mma<<<B, 512, SMEM_BYTES>>>(x, mask, qkv_b, proj_b, bt, out, nW);
}

// round 13
// speedup vs baseline: 1.5807x; 1.5707x over previous
#include <cuda_runtime.h>
#include <cuda_bf16.h>
#include <cstdint>

#define NT 49
#define CD 128

/* u16 indices into shared memory */
#define U_A    0u        /* x-A split [2][64][128] -> Q blocks -> (free) */
#define U_K    16384u    /* K blocks -> proj-A split [2][64][128] */
#define U_PA   16384u
#define U_VT   32768u    /* Vt [8 blk][32][72]; blocks 4-7 overlay spent QKV B ring */
#define U_QB0  41984u    /* QKV B ring buffers, 6144 u16 each */
#define U_QB1  48128u
#define U_PB0  32768u    /* proj B ring buffers, 8192 u16 each (Vt dead) */
#define U_PB1  40960u
#define F_BT   27136     /* f32 index: bias table 676 */
#define BYTE_RPI 111248  /* u8 rpi [2401] */
#define SMEM_BYTES 114688

#define QK_BLK 1960u     /* (h*2+sp) block stride for Q/K: 49 rows x 40 */
#define VT_BLK 2304u     /* 32 rows x 72 */

__device__ __align__(16) uint16_t g_qkvw[98304];  /* [16 chunks][192][32] permuted+split */
__device__ __align__(16) uint16_t g_projw[32768]; /* [4 chunks][128][64] split */

__device__ __forceinline__ uint32_t smem_u32(const void* p) {
    uint32_t a;
    asm("{ .reg .u64 t; cvta.to.shared.u64 t, %1; cvt.u32.u64 %0, t; }" : "=r"(a) : "l"(p));
    return a;
}
__device__ __forceinline__ void ldsm4(uint32_t* r, uint32_t a) {
    asm volatile("ldmatrix.sync.aligned.m8n8.x4.shared.b16 {%0,%1,%2,%3}, [%4];"
        : "=r"(r[0]), "=r"(r[1]), "=r"(r[2]), "=r"(r[3]) : "r"(a));
}
__device__ __forceinline__ void mma_bf16(float* d, const uint32_t* a, const uint32_t* b) {
    asm volatile("mma.sync.aligned.m16n8k16.row.col.f32.bf16.bf16.f32 "
        "{%0,%1,%2,%3}, {%4,%5,%6,%7}, {%8,%9}, {%0,%1,%2,%3};"
        : "+f"(d[0]), "+f"(d[1]), "+f"(d[2]), "+f"(d[3])
        : "r"(a[0]), "r"(a[1]), "r"(a[2]), "r"(a[3]), "r"(b[0]), "r"(b[1]));
}
__device__ __forceinline__ uint32_t pack_hi(float a, float b) {
    __nv_bfloat16 h0 = __float2bfloat16_rn(a), h1 = __float2bfloat16_rn(b);
    return (uint32_t)__bfloat16_as_ushort(h0) | ((uint32_t)__bfloat16_as_ushort(h1) << 16);
}
__device__ __forceinline__ uint32_t pack_lo(float a, float b) {
    __nv_bfloat16 h0 = __float2bfloat16_rn(a), h1 = __float2bfloat16_rn(b);
    float l0 = a - __bfloat162float(h0), l1 = b - __bfloat162float(h1);
    return (uint32_t)__bfloat16_as_ushort(__float2bfloat16_rn(l0)) |
           ((uint32_t)__bfloat16_as_ushort(__float2bfloat16_rn(l1)) << 16);
}

/* ---- prologue: split + permute weights into chunked smem-images ---- */
__global__ void prep_w(const float* __restrict__ qkv_w, const float* __restrict__ proj_w) {
    int i = blockIdx.x * blockDim.x + threadIdx.x;
    if (i < 384 * 128) {
        int n0 = i >> 7, k = i & 127;
        float f = qkv_w[i];
        __nv_bfloat16 h = __float2bfloat16_rn(f);
        __nv_bfloat16 l = __float2bfloat16_rn(f - __bfloat162float(h));
        /* column permutation: np0 = K(128-255)+V(256-319); np1 = Q(0-127)+V(320-383) */
        int np, nl;
        if (n0 >= 128 && n0 < 320) { np = 0; nl = n0 - 128; }
        else if (n0 < 128)         { np = 1; nl = n0; }
        else                       { np = 1; nl = n0 - 192; }
        int ks = k >> 5, kl = k & 31;
        int base = (np * 8 + ks * 2) * 6144 + nl * 32 + kl;
        g_qkvw[base]        = __bfloat16_as_ushort(h);
        g_qkvw[base + 6144] = __bfloat16_as_ushort(l);
    }
    if (i < 128 * 128) {
        int n = i >> 7, k = i & 127;
        float f = proj_w[i];
        __nv_bfloat16 h = __float2bfloat16_rn(f);
        __nv_bfloat16 l = __float2bfloat16_rn(f - __bfloat162float(h));
        int ks = k >> 6, kl = k & 63;
        int base = (ks * 2) * 8192 + n * 64 + kl;
        g_projw[base]        = __bfloat16_as_ushort(h);
        g_projw[base + 8192] = __bfloat16_as_ushort(l);
    }
}

/* ---- main fused kernel: 256 threads, 2 CTAs/SM ---- */
__global__ __launch_bounds__(256, 2)
void win_attn_mma(const float* __restrict__ x,
                  const float* __restrict__ mask,
                  const float* __restrict__ qkv_b,
                  const float* __restrict__ proj_b,
                  const float* __restrict__ bt,
                  float* __restrict__ out,
                  int nW)
{
    extern __shared__ float sm[];
    uint16_t* u16b = (uint16_t*)sm;
    const int t = threadIdx.x;
    const int w = blockIdx.x;
    const long base = (long)w * (NT * CD);
    const int tn = t & 31, tm = t >> 5;   /* 8 warps */
    const uint32_t smb = smem_u32(sm);

    /* ---- stage x -> A split; tables ---- */
    for (int idx = t; idx < NT * CD; idx += 256) {
        int r = idx >> 7, k = idx & 127;
        float f = x[base + idx];
        __nv_bfloat16 h = __float2bfloat16_rn(f);
        __nv_bfloat16 lo = __float2bfloat16_rn(f - __bfloat162float(h));
        int sw = ((k >> 3) ^ (r & 7)) * 8 + (k & 7);
        u16b[r * 128 + sw]        = __bfloat16_as_ushort(h);
        u16b[8192 + r * 128 + sw] = __bfloat16_as_ushort(lo);
    }
    for (int idx = t; idx < 676; idx += 256) sm[F_BT + idx] = bt[idx];
    {
        uint8_t* rpw = (uint8_t*)sm + BYTE_RPI;
        for (int idx = t; idx < NT * NT; idx += 256) {
            int i = idx / NT, j = idx - i * NT;
            int yi = i / 7, xi = i - yi * 7;
            int yj = j / 7, xj = j - yj * 7;
            rpw[idx] = (uint8_t)((yi - yj + 6) * 13 + (xi - xj + 6));
        }
    }

    const int l = tn;
    const int wm = tm & 1, wn = tm >> 1;
    const int a_r_off = l & 15;
    const int a_c_off = l >> 4;
    const int b_n_off = (l & 7) + (l >> 4) * 8;
    const int b_c_off = (l >> 3) & 1;
    const float scale = 0.1767766952966369f;

    const float4* qsrc = (const float4*)g_qkvw;
    /* stage QKV chunk 0 */
    for (int j = t; j < 768; j += 256) {
        float4 v = qsrc[j];
        int n = j >> 2, cB = j & 3;
        *(float4*)&u16b[U_QB0 + (unsigned)(n * 32) + (unsigned)((cB ^ ((n >> 1) & 3)) << 3)] = v;
    }
    __syncthreads();

    /* ======== QKV GEMM: 16 chunks, double-buffered, split-bf16 ======== */
    float dacc[2][6][4];
#pragma unroll
    for (int a = 0; a < 2; a++)
#pragma unroll
        for (int b = 0; b < 6; b++)
#pragma unroll
            for (int c = 0; c < 4; c++) dacc[a][b][c] = 0.f;

    for (int cc = 0; cc < 16; cc++) {
        const int sp = cc & 1, ks = (cc >> 1) & 3;
        const uint32_t bufb = (cc & 1) ? U_QB1 : U_QB0;
        float4 tp0, tp1, tp2;
        const bool pf = cc < 15;
        if (pf) {
            tp0 = qsrc[(cc + 1) * 768 + t];
            tp1 = qsrc[(cc + 1) * 768 + t + 256];
            tp2 = qsrc[(cc + 1) * 768 + t + 512];
        }
#pragma unroll
        for (int kk = 0; kk < 2; kk++) {
            uint32_t ahi[2][4], alo[2][4];
#pragma unroll
            for (int mt = 0; mt < 2; mt++) {
                int r = wm * 32 + mt * 16 + a_r_off;
                int ch = ks * 4 + kk * 2 + a_c_off;
                uint32_t ad = smb + (((unsigned)(r * 128) + (unsigned)(((ch ^ (r & 7))) << 3)) << 1);
                ldsm4(ahi[mt], ad);
                if (sp == 0) ldsm4(alo[mt], ad + 16384u);
            }
            uint32_t bf[6][2];
#pragma unroll
            for (int p = 0; p < 3; p++) {
                int n = wn * 48 + p * 16 + b_n_off;
                int cB = kk * 2 + b_c_off;
                uint32_t ad = smb + ((bufb + (unsigned)(n * 32) + (unsigned)((cB ^ ((n >> 1) & 3)) << 3)) << 1);
                uint32_t r4[4]; ldsm4(r4, ad);
                bf[p * 2][0] = r4[0]; bf[p * 2][1] = r4[1];
                bf[p * 2 + 1][0] = r4[2]; bf[p * 2 + 1][1] = r4[3];
            }
#pragma unroll
            for (int mt = 0; mt < 2; mt++)
#pragma unroll
                for (int nt = 0; nt < 6; nt++) {
                    mma_bf16(dacc[mt][nt], ahi[mt], bf[nt]);
                    if (sp == 0) mma_bf16(dacc[mt][nt], alo[mt], bf[nt]);
                }
        }
        if (pf) {
            uint32_t ob = ((cc + 1) & 1) ? U_QB1 : U_QB0;
            int j0 = t, n0 = j0 >> 2, c0 = j0 & 3;
            *(float4*)&u16b[ob + (unsigned)(n0 * 32) + (unsigned)((c0 ^ ((n0 >> 1) & 3)) << 3)] = tp0;
            int j1 = t + 256, n1 = j1 >> 2, c1 = j1 & 3;
            *(float4*)&u16b[ob + (unsigned)(n1 * 32) + (unsigned)((c1 ^ ((n1 >> 1) & 3)) << 3)] = tp1;
            int j2 = t + 512, n2 = j2 >> 2, c2 = j2 & 3;
            *(float4*)&u16b[ob + (unsigned)(n2 * 32) + (unsigned)((c2 ^ ((n2 >> 1) & 3)) << 3)] = tp2;
        }
        __syncthreads();

        if (cc == 7 || cc == 15) {
            /* ---- epilogue for this npass ---- */
            const int np = cc >> 3;
            int r0e = wm * 32 + (l >> 2);
#pragma unroll
            for (int mt = 0; mt < 2; mt++)
#pragma unroll
                for (int nt = 0; nt < 6; nt++)
#pragma unroll
                    for (int rh = 0; rh < 2; rh++) {
                        int row = r0e + mt * 16 + rh * 8;
                        if (row >= NT) continue;
                        int c = wn * 48 + nt * 8 + (l & 3) * 2;
                        int ob = np ? ((c < 128) ? c : 192 + c) : 128 + c;
                        float v0 = dacc[mt][nt][rh * 2]     + __ldg(qkv_b + ob);
                        float v1 = dacc[mt][nt][rh * 2 + 1] + __ldg(qkv_b + ob + 1);
                        if (c < 128 && np == 1) {          /* Q (scaled) */
                            v0 *= scale; v1 *= scale;
                            int h = c >> 5, dh = c & 31;
                            uint32_t i0 = (unsigned)(h * 2) * QK_BLK + (unsigned)(row * 40 + dh);
                            *(uint32_t*)&u16b[i0]          = pack_hi(v0, v1);
                            *(uint32_t*)&u16b[i0 + QK_BLK] = pack_lo(v0, v1);
                        } else if (c < 128) {              /* K */
                            int h = c >> 5, dh = c & 31;
                            uint32_t i0 = U_K + (unsigned)(h * 2) * QK_BLK + (unsigned)(row * 40 + dh);
                            *(uint32_t*)&u16b[i0]          = pack_hi(v0, v1);
                            *(uint32_t*)&u16b[i0 + QK_BLK] = pack_lo(v0, v1);
                        } else {                           /* V: np0->h0/1, np1->h2/3 */
                            int h = np * 2 + ((c - 128) >> 5);
                            int dh = (c - 128) & 31;
                            __nv_bfloat16 h0 = __float2bfloat16_rn(v0);
                            __nv_bfloat16 h1 = __float2bfloat16_rn(v1);
                            __nv_bfloat16 l0 = __float2bfloat16_rn(v0 - __bfloat162float(h0));
                            __nv_bfloat16 l1 = __float2bfloat16_rn(v1 - __bfloat162float(h1));
                            uint32_t bh = U_VT + (unsigned)(h * 2) * VT_BLK + (unsigned)(dh * 72 + row);
                            u16b[bh]           = __bfloat16_as_ushort(h0);
                            u16b[bh + 72]      = __bfloat16_as_ushort(h1);
                            u16b[bh + VT_BLK]      = __bfloat16_as_ushort(l0);
                            u16b[bh + VT_BLK + 72] = __bfloat16_as_ushort(l1);
                        }
                    }
            if (np == 0) {
#pragma unroll
                for (int a = 0; a < 2; a++)
#pragma unroll
                    for (int b = 0; b < 6; b++)
#pragma unroll
                        for (int c = 0; c < 4; c++) dacc[a][b][c] = 0.f;
            }
        }
    }
    /* zero Vt key-pad cols 49..63 (P pads are exact zeros; V pads must be finite) */
    for (int i = t; i < 3840; i += 256) {
        int blk = i / 480, rem = i - blk * 480;
        int dh = rem / 15, jj = rem - dh * 15;
        u16b[U_VT + (unsigned)blk * VT_BLK + (unsigned)(dh * 72 + 49 + jj)] = 0;
    }
    __syncthreads();

    /* ======== attention, register-resident: 8 warps = 4 heads x 2 m-halves ======== */
    const float* mrow = mask + (long)(w % nW) * (NT * NT);
    const uint8_t* rp = (const uint8_t*)sm + BYTE_RPI;
    const int h = tm >> 1, half = tm & 1;
    const int cbase = (l & 3) * 2;

    float oacc[2][4][4];
#pragma unroll
    for (int a = 0; a < 2; a++)
#pragma unroll
        for (int b = 0; b < 4; b++)
#pragma unroll
            for (int c = 0; c < 4; c++) oacc[a][b][c] = 0.f;

#pragma unroll
    for (int s2 = 0; s2 < 2; s2++) {
        const int mt = half * 2 + s2;
        const int r0 = mt * 16 + (l >> 2);
        const int r1 = r0 + 8;

        float sacc[8][4];
#pragma unroll
        for (int a = 0; a < 8; a++)
#pragma unroll
            for (int c = 0; c < 4; c++) sacc[a][c] = 0.f;

#pragma unroll
        for (int kk = 0; kk < 2; kk++) {
            uint32_t aq[2][4];
#pragma unroll
            for (int sp = 0; sp < 2; sp++)
                ldsm4(aq[sp], smb + (((unsigned)(h * 2 + sp) * QK_BLK +
                    (unsigned)((mt * 16 + a_r_off) * 40 + (kk * 2 + a_c_off) * 8)) << 1));
            uint32_t bk[8][2][2];
#pragma unroll
            for (int g = 0; g < 4; g++)
#pragma unroll
                for (int sp = 0; sp < 2; sp++) {
                    uint32_t r4[4];
                    ldsm4(r4, smb + ((U_K + (unsigned)(h * 2 + sp) * QK_BLK +
                        (unsigned)((g * 16 + b_n_off) * 40 + (kk * 2 + b_c_off) * 8)) << 1));
                    bk[g * 2][sp][0] = r4[0]; bk[g * 2][sp][1] = r4[1];
                    bk[g * 2 + 1][sp][0] = r4[2]; bk[g * 2 + 1][sp][1] = r4[3];
                }
#pragma unroll
            for (int nt = 0; nt < 8; nt++) {
                mma_bf16(sacc[nt], aq[0], bk[nt][0]);
                mma_bf16(sacc[nt], aq[0], bk[nt][1]);
                mma_bf16(sacc[nt], aq[1], bk[nt][0]);
            }
        }

        /* softmax in registers (+bias+mask) */
        {
            int r0c = (r0 < NT) ? r0 : (NT - 1);
            int r1c = (r1 < NT) ? r1 : (NT - 1);
            float m0 = -1e30f, m1 = -1e30f;
#pragma unroll
            for (int nt = 0; nt < 8; nt++)
#pragma unroll
                for (int j = 0; j < 2; j++) {
                    int c = nt * 8 + cbase + j;
                    if (c < NT) {
                        float bi0 = sm[F_BT + rp[r0c * NT + c] * 4 + h];
                        float bi1 = sm[F_BT + rp[r1c * NT + c] * 4 + h];
                        float mk0 = (r0 < NT) ? mrow[r0 * NT + c] : 0.f;
                        float mk1 = (r1 < NT) ? mrow[r1 * NT + c] : 0.f;
                        sacc[nt][j]     += bi0 + mk0;
                        sacc[nt][2 + j] += bi1 + mk1;
                    } else {
                        sacc[nt][j] = -1e30f;
                        sacc[nt][2 + j] = -1e30f;
                    }
                    m0 = fmaxf(m0, sacc[nt][j]);
                    m1 = fmaxf(m1, sacc[nt][2 + j]);
                }
            m0 = fmaxf(m0, __shfl_xor_sync(0xffffffffu, m0, 1));
            m0 = fmaxf(m0, __shfl_xor_sync(0xffffffffu, m0, 2));
            m1 = fmaxf(m1, __shfl_xor_sync(0xffffffffu, m1, 1));
            m1 = fmaxf(m1, __shfl_xor_sync(0xffffffffu, m1, 2));
            float s0 = 0.f, s1 = 0.f;
#pragma unroll
            for (int nt = 0; nt < 8; nt++)
#pragma unroll
                for (int j = 0; j < 2; j++) {
                    float e0 = __expf(sacc[nt][j] - m0);
                    float e1 = __expf(sacc[nt][2 + j] - m1);
                    sacc[nt][j] = e0; sacc[nt][2 + j] = e1;
                    s0 += e0; s1 += e1;
                }
            s0 += __shfl_xor_sync(0xffffffffu, s0, 1);
            s0 += __shfl_xor_sync(0xffffffffu, s0, 2);
            s1 += __shfl_xor_sync(0xffffffffu, s1, 1);
            s1 += __shfl_xor_sync(0xffffffffu, s1, 2);
            float i0 = 1.f / s0, i1 = 1.f / s1;
#pragma unroll
            for (int nt = 0; nt < 8; nt++)
#pragma unroll
                for (int j = 0; j < 2; j++) { sacc[nt][j] *= i0; sacc[nt][2 + j] *= i1; }
        }

        /* PV: P straight from registers */
#pragma unroll
        for (int kt = 0; kt < 4; kt++) {
            uint32_t ah[4], al[4];
            ah[0] = pack_hi(sacc[2 * kt][0], sacc[2 * kt][1]);
            ah[1] = pack_hi(sacc[2 * kt][2], sacc[2 * kt][3]);
            ah[2] = pack_hi(sacc[2 * kt + 1][0], sacc[2 * kt + 1][1]);
            ah[3] = pack_hi(sacc[2 * kt + 1][2], sacc[2 * kt + 1][3]);
            al[0] = pack_lo(sacc[2 * kt][0], sacc[2 * kt][1]);
            al[1] = pack_lo(sacc[2 * kt][2], sacc[2 * kt][3]);
            al[2] = pack_lo(sacc[2 * kt + 1][0], sacc[2 * kt + 1][1]);
            al[3] = pack_lo(sacc[2 * kt + 1][2], sacc[2 * kt + 1][3]);
            uint32_t bv[4][2][2];
#pragma unroll
            for (int g = 0; g < 2; g++)
#pragma unroll
                for (int sp = 0; sp < 2; sp++) {
                    uint32_t r4[4];
                    ldsm4(r4, smb + ((U_VT + (unsigned)(h * 2 + sp) * VT_BLK +
                        (unsigned)((g * 16 + b_n_off) * 72 + kt * 16 + b_c_off * 8)) << 1));
                    bv[g * 2][sp][0] = r4[0]; bv[g * 2][sp][1] = r4[1];
                    bv[g * 2 + 1][sp][0] = r4[2]; bv[g * 2 + 1][sp][1] = r4[3];
                }
#pragma unroll
            for (int n = 0; n < 4; n++) {
                mma_bf16(oacc[s2][n], ah, bv[n][0]);
                mma_bf16(oacc[s2][n], ah, bv[n][1]);
                mma_bf16(oacc[s2][n], al, bv[n][0]);
            }
        }
    }
    __syncthreads();   /* all Q/K/Vt reads done */

    /* ---- O fragments -> proj-A split (overlays K region) ---- */
#pragma unroll
    for (int s2 = 0; s2 < 2; s2++)
#pragma unroll
        for (int n = 0; n < 4; n++)
#pragma unroll
            for (int rh = 0; rh < 2; rh++) {
                int row = (half * 2 + s2) * 16 + (l >> 2) + rh * 8;
                int c = h * 32 + n * 8 + cbase;
                int sw = ((c >> 3) ^ (row & 7)) * 8 + (c & 7);
                *(uint32_t*)&u16b[U_PA + (unsigned)(row * 128 + sw)] =
                    pack_hi(oacc[s2][n][rh * 2], oacc[s2][n][rh * 2 + 1]);
                *(uint32_t*)&u16b[U_PA + 8192u + (unsigned)(row * 128 + sw)] =
                    pack_lo(oacc[s2][n][rh * 2], oacc[s2][n][rh * 2 + 1]);
            }
    /* stage proj chunk 0 (overlays dead Vt) */
    const float4* psrc = (const float4*)g_projw;
    for (int j = t; j < 1024; j += 256) {
        float4 v = psrc[j];
        int n = j >> 3, cB = j & 7;
        *(float4*)&u16b[U_PB0 + (unsigned)(n * 64) + (unsigned)((cB ^ (n & 7)) << 3)] = v;
    }
    __syncthreads();

    /* ======== proj GEMM: 4 chunks, double-buffered, split-bf16 ======== */
    float pacc[2][4][4];
#pragma unroll
    for (int a = 0; a < 2; a++)
#pragma unroll
        for (int b = 0; b < 4; b++)
#pragma unroll
            for (int c = 0; c < 4; c++) pacc[a][b][c] = 0.f;

    for (int cc = 0; cc < 4; cc++) {
        const int sp = cc & 1, ks = cc >> 1;
        const uint32_t bufb = (cc & 1) ? U_PB1 : U_PB0;
        float4 tp[4];
        const bool pf = cc < 3;
        if (pf) {
#pragma unroll
            for (int i = 0; i < 4; i++) tp[i] = psrc[(cc + 1) * 1024 + t + i * 256];
        }
#pragma unroll
        for (int kk = 0; kk < 4; kk++) {
            uint32_t ahi[2][4], alo[2][4];
#pragma unroll
            for (int mt = 0; mt < 2; mt++) {
                int r = wm * 32 + mt * 16 + a_r_off;
                int ch = ks * 8 + kk * 2 + a_c_off;
                uint32_t ad = smb + ((U_PA + (unsigned)(r * 128) + (unsigned)((ch ^ (r & 7)) << 3)) << 1);
                ldsm4(ahi[mt], ad);
                if (sp == 0) ldsm4(alo[mt], ad + 16384u);
            }
            uint32_t bf2[4][2];
#pragma unroll
            for (int p2 = 0; p2 < 2; p2++) {
                int n = wn * 32 + p2 * 16 + b_n_off;
                int cB = kk * 2 + b_c_off;
                uint32_t ad = smb + ((bufb + (unsigned)(n * 64) + (unsigned)((cB ^ (n & 7)) << 3)) << 1);
                uint32_t r4[4]; ldsm4(r4, ad);
                bf2[p2 * 2][0] = r4[0]; bf2[p2 * 2][1] = r4[1];
                bf2[p2 * 2 + 1][0] = r4[2]; bf2[p2 * 2 + 1][1] = r4[3];
            }
#pragma unroll
            for (int mt = 0; mt < 2; mt++)
#pragma unroll
                for (int nt = 0; nt < 4; nt++) {
                    mma_bf16(pacc[mt][nt], ahi[mt], bf2[nt]);
                    if (sp == 0) mma_bf16(pacc[mt][nt], alo[mt], bf2[nt]);
                }
        }
        if (pf) {
            uint32_t ob = ((cc + 1) & 1) ? U_PB1 : U_PB0;
#pragma unroll
            for (int i = 0; i < 4; i++) {
                int j = t + i * 256, n = j >> 3, cB = j & 7;
                *(float4*)&u16b[ob + (unsigned)(n * 64) + (unsigned)((cB ^ (n & 7)) << 3)] = tp[i];
            }
        }
        __syncthreads();
    }

    /* ---- epilogue: direct fragment stores (+bias) ---- */
#pragma unroll
    for (int mt = 0; mt < 2; mt++)
#pragma unroll
        for (int nt = 0; nt < 4; nt++)
#pragma unroll
            for (int rh = 0; rh < 2; rh++) {
                int row = wm * 32 + mt * 16 + (l >> 2) + rh * 8;
                if (row < NT) {
                    int col = wn * 32 + nt * 8 + cbase;
                    float2 v;
                    v.x = pacc[mt][nt][rh * 2]     + __ldg(proj_b + col);
                    v.y = pacc[mt][nt][rh * 2 + 1] + __ldg(proj_b + col + 1);
                    *(float2*)&out[base + row * CD + col] = v;
                }
            }
}

extern "C" void kernel_launch(void* const* d_in, const int* in_sizes, int n_in,
                              void* d_out, int out_size) {
    const float* x      = (const float*)d_in[0];
    const float* mask   = (const float*)d_in[1];
    const float* qkv_w  = (const float*)d_in[2];
    const float* qkv_b  = (const float*)d_in[3];
    const float* proj_w = (const float*)d_in[4];
    const float* proj_b = (const float*)d_in[5];
    const float* bt     = (const float*)d_in[6];
    float* out = (float*)d_out;

    int B  = in_sizes[0] / (NT * CD);     /* 16384 */
    int nW = in_sizes[1] / (NT * NT);     /* 1024 */

    prep_w<<<96, 512>>>(qkv_w, proj_w);

    cudaFuncSetAttribute(win_attn_mma,
                         cudaFuncAttributeMaxDynamicSharedMemorySize, SMEM_BYTES);
    win_attn_mma<<<B, 256, SMEM_BYTES>>>(x, mask, qkv_b, proj_b, bt, out, nW);
}

// round 14
// speedup vs baseline: 1.6104x; 1.0188x over previous
#include <cuda_runtime.h>
#include <cuda_bf16.h>
#include <cstdint>

#define NT 49
#define CD 128

/* u16 indices into shared memory */
#define U_A    0u        /* x-A split [2][64][128] -> Q blocks overlay */
#define U_K    16384u    /* K blocks -> proj-A split [2][64][128] */
#define U_PA   16384u
#define U_V    32768u    /* V row-major [8 blk][64][40]; h2/h3 blocks overlay spent ring */
#define U_QB0  43008u    /* QKV B ring buffers, 6144 u16 each */
#define U_QB1  49152u
#define U_PB0  32768u    /* proj B ring buffers, 8192 u16 each (V dead) */
#define U_PB1  40960u
#define RPI_BYTE 110592  /* u8 rpi [2401] */
#define SMEM_BYTES 114688

#define QK_BLK 1960u     /* (h*2+sp) block stride for Q/K: 49 rows x 40 */
#define V_BLK  2560u     /* 64 rows x 40 */

__device__ __align__(16) uint16_t g_qkvw[98304];  /* [16 chunks][pre-swizzled 6144] */
__device__ __align__(16) uint16_t g_projw[32768]; /* [4 chunks][pre-swizzled 8192] */

__device__ __forceinline__ uint32_t smem_u32(const void* p) {
    uint32_t a;
    asm("{ .reg .u64 t; cvta.to.shared.u64 t, %1; cvt.u32.u64 %0, t; }" : "=r"(a) : "l"(p));
    return a;
}
__device__ __forceinline__ void ldsm4(uint32_t* r, uint32_t a) {
    asm volatile("ldmatrix.sync.aligned.m8n8.x4.shared.b16 {%0,%1,%2,%3}, [%4];"
        : "=r"(r[0]), "=r"(r[1]), "=r"(r[2]), "=r"(r[3]) : "r"(a));
}
__device__ __forceinline__ void ldsm4t(uint32_t* r, uint32_t a) {
    asm volatile("ldmatrix.sync.aligned.m8n8.x4.trans.shared.b16 {%0,%1,%2,%3}, [%4];"
        : "=r"(r[0]), "=r"(r[1]), "=r"(r[2]), "=r"(r[3]) : "r"(a));
}
__device__ __forceinline__ void mma_bf16(float* d, const uint32_t* a, const uint32_t* b) {
    asm volatile("mma.sync.aligned.m16n8k16.row.col.f32.bf16.bf16.f32 "
        "{%0,%1,%2,%3}, {%4,%5,%6,%7}, {%8,%9}, {%0,%1,%2,%3};"
        : "+f"(d[0]), "+f"(d[1]), "+f"(d[2]), "+f"(d[3])
        : "r"(a[0]), "r"(a[1]), "r"(a[2]), "r"(a[3]), "r"(b[0]), "r"(b[1]));
}
__device__ __forceinline__ uint32_t pack_hi(float a, float b) {
    __nv_bfloat16 h0 = __float2bfloat16_rn(a), h1 = __float2bfloat16_rn(b);
    return (uint32_t)__bfloat16_as_ushort(h0) | ((uint32_t)__bfloat16_as_ushort(h1) << 16);
}
__device__ __forceinline__ uint32_t pack_lo(float a, float b) {
    __nv_bfloat16 h0 = __float2bfloat16_rn(a), h1 = __float2bfloat16_rn(b);
    float l0 = a - __bfloat162float(h0), l1 = b - __bfloat162float(h1);
    return (uint32_t)__bfloat16_as_ushort(__float2bfloat16_rn(l0)) |
           ((uint32_t)__bfloat16_as_ushort(__float2bfloat16_rn(l1)) << 16);
}

/* ---- prologue: split + permute + PRE-SWIZZLE weights (staging = linear memcpy) ---- */
__global__ void prep_w(const float* __restrict__ qkv_w, const float* __restrict__ proj_w) {
    int i = blockIdx.x * blockDim.x + threadIdx.x;
    if (i < 384 * 128) {
        int n0 = i >> 7, k = i & 127;
        float f = qkv_w[i];
        __nv_bfloat16 h = __float2bfloat16_rn(f);
        __nv_bfloat16 l = __float2bfloat16_rn(f - __bfloat162float(h));
        /* column permutation: np0 = K(128-255)+V(256-319); np1 = Q(0-127)+V(320-383) */
        int np, nl;
        if (n0 >= 128 && n0 < 320) { np = 0; nl = n0 - 128; }
        else if (n0 < 128)         { np = 1; nl = n0; }
        else                       { np = 1; nl = n0 - 192; }
        int ks = k >> 5, kl = k & 31;
        int pos = nl * 32 + ((((kl >> 3) ^ ((nl >> 1) & 3))) << 3) + (kl & 7);  /* baked swizzle */
        int base = (np * 8 + ks * 2) * 6144 + pos;
        g_qkvw[base]        = __bfloat16_as_ushort(h);
        g_qkvw[base + 6144] = __bfloat16_as_ushort(l);
    }
    if (i < 128 * 128) {
        int n = i >> 7, k = i & 127;
        float f = proj_w[i];
        __nv_bfloat16 h = __float2bfloat16_rn(f);
        __nv_bfloat16 l = __float2bfloat16_rn(f - __bfloat162float(h));
        int ks = k >> 6, kl = k & 63;
        int pos = n * 64 + ((((kl >> 3) ^ (n & 7))) << 3) + (kl & 7);           /* baked swizzle */
        int base = (ks * 2) * 8192 + pos;
        g_projw[base]        = __bfloat16_as_ushort(h);
        g_projw[base + 8192] = __bfloat16_as_ushort(l);
    }
}

/* ---- main fused kernel: 256 threads, 2 CTAs/SM ---- */
__global__ __launch_bounds__(256, 2)
void win_attn_mma(const float* __restrict__ x,
                  const float* __restrict__ mask,
                  const float* __restrict__ qkv_b,
                  const float* __restrict__ proj_b,
                  const float* __restrict__ bt,
                  float* __restrict__ out,
                  int nW)
{
    extern __shared__ float sm[];
    uint16_t* u16b = (uint16_t*)sm;
    const int t = threadIdx.x;
    const int w = blockIdx.x;
    const long base = (long)w * (NT * CD);
    const int tn = t & 31, tm = t >> 5;   /* 8 warps */
    const uint32_t smb = smem_u32(sm);

    /* ---- stage x -> A split; rpi table ---- */
    for (int idx = t; idx < NT * CD; idx += 256) {
        int r = idx >> 7, k = idx & 127;
        float f = x[base + idx];
        __nv_bfloat16 h = __float2bfloat16_rn(f);
        __nv_bfloat16 lo = __float2bfloat16_rn(f - __bfloat162float(h));
        int sw = ((k >> 3) ^ (r & 7)) * 8 + (k & 7);
        u16b[r * 128 + sw]        = __bfloat16_as_ushort(h);
        u16b[8192 + r * 128 + sw] = __bfloat16_as_ushort(lo);
    }
    {
        uint8_t* rpw = (uint8_t*)sm + RPI_BYTE;
        for (int idx = t; idx < NT * NT; idx += 256) {
            int i = idx / NT, j = idx - i * NT;
            int yi = i / 7, xi = i - yi * 7;
            int yj = j / 7, xj = j - yj * 7;
            rpw[idx] = (uint8_t)((yi - yj + 6) * 13 + (xi - xj + 6));
        }
    }

    const int l = tn;
    const int wm = tm & 1, wn = tm >> 1;
    const int a_r_off = l & 15;
    const int a_c_off = l >> 4;
    const int b_n_off = (l & 7) + (l >> 4) * 8;
    const int b_c_off = (l >> 3) & 1;
    const float scale = 0.1767766952966369f;

    const float4* qsrc = (const float4*)g_qkvw;
    /* stage QKV chunk 0: pure linear copy (swizzle baked into image) */
    {
        float4* dst = (float4*)u16b + (U_QB0 >> 3);
        for (int j = t; j < 768; j += 256) dst[j] = qsrc[j];
    }
    __syncthreads();

    /* ======== QKV GEMM: 16 chunks, double-buffered, split-bf16 ======== */
    float dacc[2][6][4];
#pragma unroll
    for (int a = 0; a < 2; a++)
#pragma unroll
        for (int b = 0; b < 6; b++)
#pragma unroll
            for (int c = 0; c < 4; c++) dacc[a][b][c] = 0.f;

    for (int cc = 0; cc < 16; cc++) {
        const int sp = cc & 1, ks = (cc >> 1) & 3;
        const uint32_t bufb = (cc & 1) ? U_QB1 : U_QB0;
        float4 tp0, tp1, tp2;
        const bool pf = cc < 15;
        if (pf) {
            tp0 = qsrc[(cc + 1) * 768 + t];
            tp1 = qsrc[(cc + 1) * 768 + t + 256];
            tp2 = qsrc[(cc + 1) * 768 + t + 512];
        }
#pragma unroll
        for (int kk = 0; kk < 2; kk++) {
            uint32_t ahi[2][4], alo[2][4];
#pragma unroll
            for (int mt = 0; mt < 2; mt++) {
                int r = wm * 32 + mt * 16 + a_r_off;
                int ch = ks * 4 + kk * 2 + a_c_off;
                uint32_t ad = smb + (((unsigned)(r * 128) + (unsigned)(((ch ^ (r & 7))) << 3)) << 1);
                ldsm4(ahi[mt], ad);
                if (sp == 0) ldsm4(alo[mt], ad + 16384u);
            }
            uint32_t bf[6][2];
#pragma unroll
            for (int p = 0; p < 3; p++) {
                int n = wn * 48 + p * 16 + b_n_off;
                int cB = kk * 2 + b_c_off;
                uint32_t ad = smb + ((bufb + (unsigned)(n * 32) + (unsigned)((cB ^ ((n >> 1) & 3)) << 3)) << 1);
                uint32_t r4[4]; ldsm4(r4, ad);
                bf[p * 2][0] = r4[0]; bf[p * 2][1] = r4[1];
                bf[p * 2 + 1][0] = r4[2]; bf[p * 2 + 1][1] = r4[3];
            }
#pragma unroll
            for (int mt = 0; mt < 2; mt++)
#pragma unroll
                for (int nt = 0; nt < 6; nt++) {
                    mma_bf16(dacc[mt][nt], ahi[mt], bf[nt]);
                    if (sp == 0) mma_bf16(dacc[mt][nt], alo[mt], bf[nt]);
                }
        }
        if (pf) {
            float4* dst = (float4*)u16b + ((((cc + 1) & 1) ? U_QB1 : U_QB0) >> 3);
            dst[t] = tp0; dst[t + 256] = tp1; dst[t + 512] = tp2;
        }
        __syncthreads();

        if (cc == 7 || cc == 15) {
            /* ---- epilogue for this npass ---- */
            const int np = cc >> 3;
            int r0e = wm * 32 + (l >> 2);
#pragma unroll
            for (int mt = 0; mt < 2; mt++)
#pragma unroll
                for (int nt = 0; nt < 6; nt++)
#pragma unroll
                    for (int rh = 0; rh < 2; rh++) {
                        int row = r0e + mt * 16 + rh * 8;
                        if (row >= NT) continue;
                        int c = wn * 48 + nt * 8 + (l & 3) * 2;
                        int ob = np ? ((c < 128) ? c : 192 + c) : 128 + c;
                        float v0 = dacc[mt][nt][rh * 2]     + __ldg(qkv_b + ob);
                        float v1 = dacc[mt][nt][rh * 2 + 1] + __ldg(qkv_b + ob + 1);
                        if (c < 128 && np == 1) {          /* Q (scaled) */
                            v0 *= scale; v1 *= scale;
                            int h = c >> 5, dh = c & 31;
                            uint32_t i0 = (unsigned)(h * 2) * QK_BLK + (unsigned)(row * 40 + dh);
                            *(uint32_t*)&u16b[i0]          = pack_hi(v0, v1);
                            *(uint32_t*)&u16b[i0 + QK_BLK] = pack_lo(v0, v1);
                        } else if (c < 128) {              /* K [n=token][k=dh] */
                            int h = c >> 5, dh = c & 31;
                            uint32_t i0 = U_K + (unsigned)(h * 2) * QK_BLK + (unsigned)(row * 40 + dh);
                            *(uint32_t*)&u16b[i0]          = pack_hi(v0, v1);
                            *(uint32_t*)&u16b[i0 + QK_BLK] = pack_lo(v0, v1);
                        } else {                           /* V row-major [j=token][dh] */
                            int h = np * 2 + ((c - 128) >> 5);
                            int dh = (c - 128) & 31;
                            uint32_t vb = U_V + (unsigned)(h * 2) * V_BLK + (unsigned)(row * 40 + dh);
                            *(uint32_t*)&u16b[vb]         = pack_hi(v0, v1);
                            *(uint32_t*)&u16b[vb + V_BLK] = pack_lo(v0, v1);
                        }
                    }
            if (np == 0) {
#pragma unroll
                for (int a = 0; a < 2; a++)
#pragma unroll
                    for (int b = 0; b < 6; b++)
#pragma unroll
                        for (int c = 0; c < 4; c++) dacc[a][b][c] = 0.f;
            }
        }
    }
    /* zero V pad rows 49..63 (dh 0..31), all 8 blocks, vectorized u32 */
    for (int i = t; i < 1920; i += 256) {
        int blk = i / 240, rem = i - blk * 240;
        int rr = rem >> 4, dhp = rem & 15;
        *(uint32_t*)&u16b[U_V + (unsigned)blk * V_BLK + (unsigned)((49 + rr) * 40 + dhp * 2)] = 0u;
    }
    __syncthreads();

    /* ======== attention, register-resident: 8 warps = 4 heads x 2 m-halves ======== */
    const float* mrow = mask + (long)(w % nW) * (NT * NT);
    const uint8_t* rp = (const uint8_t*)sm + RPI_BYTE;
    const int h = tm >> 1, half = tm & 1;
    const int cbase = (l & 3) * 2;

    float oacc[2][4][4];
#pragma unroll
    for (int a = 0; a < 2; a++)
#pragma unroll
        for (int b = 0; b < 4; b++)
#pragma unroll
            for (int c = 0; c < 4; c++) oacc[a][b][c] = 0.f;

#pragma unroll
    for (int s2 = 0; s2 < 2; s2++) {
        const int mt = half * 2 + s2;
        const int r0 = mt * 16 + (l >> 2);
        const int r1 = r0 + 8;

        float sacc[8][4];
#pragma unroll
        for (int a = 0; a < 8; a++)
#pragma unroll
            for (int c = 0; c < 4; c++) sacc[a][c] = 0.f;

#pragma unroll
        for (int kk = 0; kk < 2; kk++) {
            uint32_t aq[2][4];
#pragma unroll
            for (int sp = 0; sp < 2; sp++)
                ldsm4(aq[sp], smb + (((unsigned)(h * 2 + sp) * QK_BLK +
                    (unsigned)((mt * 16 + a_r_off) * 40 + (kk * 2 + a_c_off) * 8)) << 1));
            uint32_t bk[8][2][2];
#pragma unroll
            for (int g = 0; g < 4; g++)
#pragma unroll
                for (int sp = 0; sp < 2; sp++) {
                    uint32_t r4[4];
                    ldsm4(r4, smb + ((U_K + (unsigned)(h * 2 + sp) * QK_BLK +
                        (unsigned)((g * 16 + b_n_off) * 40 + (kk * 2 + b_c_off) * 8)) << 1));
                    bk[g * 2][sp][0] = r4[0]; bk[g * 2][sp][1] = r4[1];
                    bk[g * 2 + 1][sp][0] = r4[2]; bk[g * 2 + 1][sp][1] = r4[3];
                }
#pragma unroll
            for (int nt = 0; nt < 8; nt++) {
                mma_bf16(sacc[nt], aq[0], bk[nt][0]);
                mma_bf16(sacc[nt], aq[0], bk[nt][1]);
                mma_bf16(sacc[nt], aq[1], bk[nt][0]);
            }
        }

        /* softmax in registers (+bias via __ldg +mask) */
        {
            int r0c = (r0 < NT) ? r0 : (NT - 1);
            int r1c = (r1 < NT) ? r1 : (NT - 1);
            float m0 = -1e30f, m1 = -1e30f;
#pragma unroll
            for (int nt = 0; nt < 8; nt++)
#pragma unroll
                for (int j = 0; j < 2; j++) {
                    int c = nt * 8 + cbase + j;
                    if (c < NT) {
                        float bi0 = __ldg(bt + rp[r0c * NT + c] * 4 + h);
                        float bi1 = __ldg(bt + rp[r1c * NT + c] * 4 + h);
                        float mk0 = (r0 < NT) ? mrow[r0 * NT + c] : 0.f;
                        float mk1 = (r1 < NT) ? mrow[r1 * NT + c] : 0.f;
                        sacc[nt][j]     += bi0 + mk0;
                        sacc[nt][2 + j] += bi1 + mk1;
                    } else {
                        sacc[nt][j] = -1e30f;
                        sacc[nt][2 + j] = -1e30f;
                    }
                    m0 = fmaxf(m0, sacc[nt][j]);
                    m1 = fmaxf(m1, sacc[nt][2 + j]);
                }
            m0 = fmaxf(m0, __shfl_xor_sync(0xffffffffu, m0, 1));
            m0 = fmaxf(m0, __shfl_xor_sync(0xffffffffu, m0, 2));
            m1 = fmaxf(m1, __shfl_xor_sync(0xffffffffu, m1, 1));
            m1 = fmaxf(m1, __shfl_xor_sync(0xffffffffu, m1, 2));
            float s0 = 0.f, s1 = 0.f;
#pragma unroll
            for (int nt = 0; nt < 8; nt++)
#pragma unroll
                for (int j = 0; j < 2; j++) {
                    float e0 = __expf(sacc[nt][j] - m0);
                    float e1 = __expf(sacc[nt][2 + j] - m1);
                    sacc[nt][j] = e0; sacc[nt][2 + j] = e1;
                    s0 += e0; s1 += e1;
                }
            s0 += __shfl_xor_sync(0xffffffffu, s0, 1);
            s0 += __shfl_xor_sync(0xffffffffu, s0, 2);
            s1 += __shfl_xor_sync(0xffffffffu, s1, 1);
            s1 += __shfl_xor_sync(0xffffffffu, s1, 2);
            float i0 = 1.f / s0, i1 = 1.f / s1;
#pragma unroll
            for (int nt = 0; nt < 8; nt++)
#pragma unroll
                for (int j = 0; j < 2; j++) { sacc[nt][j] *= i0; sacc[nt][2 + j] *= i1; }
        }

        /* PV: P straight from registers; V via ldmatrix.trans on row-major V */
#pragma unroll
        for (int kt = 0; kt < 4; kt++) {
            uint32_t ah[4], al[4];
            ah[0] = pack_hi(sacc[2 * kt][0], sacc[2 * kt][1]);
            ah[1] = pack_hi(sacc[2 * kt][2], sacc[2 * kt][3]);
            ah[2] = pack_hi(sacc[2 * kt + 1][0], sacc[2 * kt + 1][1]);
            ah[3] = pack_hi(sacc[2 * kt + 1][2], sacc[2 * kt + 1][3]);
            al[0] = pack_lo(sacc[2 * kt][0], sacc[2 * kt][1]);
            al[1] = pack_lo(sacc[2 * kt][2], sacc[2 * kt][3]);
            al[2] = pack_lo(sacc[2 * kt + 1][0], sacc[2 * kt + 1][1]);
            al[3] = pack_lo(sacc[2 * kt + 1][2], sacc[2 * kt + 1][3]);
            uint32_t bv[4][2][2];
#pragma unroll
            for (int g = 0; g < 2; g++)
#pragma unroll
                for (int sp = 0; sp < 2; sp++) {
                    uint32_t r4[4];
                    /* lanes: j = kt*16 + (l&15), dh = g*16 + (l>>4)*8 */
                    ldsm4t(r4, smb + ((U_V + (unsigned)(h * 2 + sp) * V_BLK +
                        (unsigned)((kt * 16 + a_r_off) * 40 + g * 16 + a_c_off * 8)) << 1));
                    bv[g * 2][sp][0] = r4[0]; bv[g * 2][sp][1] = r4[1];
                    bv[g * 2 + 1][sp][0] = r4[2]; bv[g * 2 + 1][sp][1] = r4[3];
                }
#pragma unroll
            for (int n = 0; n < 4; n++) {
                mma_bf16(oacc[s2][n], ah, bv[n][0]);
                mma_bf16(oacc[s2][n], ah, bv[n][1]);
                mma_bf16(oacc[s2][n], al, bv[n][0]);
            }
        }
    }
    __syncthreads();   /* all Q/K/V reads done */

    /* ---- O fragments -> proj-A split (overlays K region) ---- */
#pragma unroll
    for (int s2 = 0; s2 < 2; s2++)
#pragma unroll
        for (int n = 0; n < 4; n++)
#pragma unroll
            for (int rh = 0; rh < 2; rh++) {
                int row = (half * 2 + s2) * 16 + (l >> 2) + rh * 8;
                int c = h * 32 + n * 8 + cbase;
                int sw = ((c >> 3) ^ (row & 7)) * 8 + (c & 7);
                *(uint32_t*)&u16b[U_PA + (unsigned)(row * 128 + sw)] =
                    pack_hi(oacc[s2][n][rh * 2], oacc[s2][n][rh * 2 + 1]);
                *(uint32_t*)&u16b[U_PA + 8192u + (unsigned)(row * 128 + sw)] =
                    pack_lo(oacc[s2][n][rh * 2], oacc[s2][n][rh * 2 + 1]);
            }
    /* stage proj chunk 0: linear copy (swizzle baked) */
    const float4* psrc = (const float4*)g_projw;
    {
        float4* dst = (float4*)u16b + (U_PB0 >> 3);
        for (int j = t; j < 1024; j += 256) dst[j] = psrc[j];
    }
    __syncthreads();

    /* ======== proj GEMM: 4 chunks, double-buffered, split-bf16 ======== */
    float pacc[2][4][4];
#pragma unroll
    for (int a = 0; a < 2; a++)
#pragma unroll
        for (int b = 0; b < 4; b++)
#pragma unroll
            for (int c = 0; c < 4; c++) pacc[a][b][c] = 0.f;

    for (int cc = 0; cc < 4; cc++) {
        const int sp = cc & 1, ks = cc >> 1;
        const uint32_t bufb = (cc & 1) ? U_PB1 : U_PB0;
        float4 tp[4];
        const bool pf = cc < 3;
        if (pf) {
#pragma unroll
            for (int i = 0; i < 4; i++) tp[i] = psrc[(cc + 1) * 1024 + t + i * 256];
        }
#pragma unroll
        for (int kk = 0; kk < 4; kk++) {
            uint32_t ahi[2][4], alo[2][4];
#pragma unroll
            for (int mt = 0; mt < 2; mt++) {
                int r = wm * 32 + mt * 16 + a_r_off;
                int ch = ks * 8 + kk * 2 + a_c_off;
                uint32_t ad = smb + ((U_PA + (unsigned)(r * 128) + (unsigned)((ch ^ (r & 7)) << 3)) << 1);
                ldsm4(ahi[mt], ad);
                if (sp == 0) ldsm4(alo[mt], ad + 16384u);
            }
            uint32_t bf2[4][2];
#pragma unroll
            for (int p2 = 0; p2 < 2; p2++) {
                int n = wn * 32 + p2 * 16 + b_n_off;
                int cB = kk * 2 + b_c_off;
                uint32_t ad = smb + ((bufb + (unsigned)(n * 64) + (unsigned)((cB ^ (n & 7)) << 3)) << 1);
                uint32_t r4[4]; ldsm4(r4, ad);
                bf2[p2 * 2][0] = r4[0]; bf2[p2 * 2][1] = r4[1];
                bf2[p2 * 2 + 1][0] = r4[2]; bf2[p2 * 2 + 1][1] = r4[3];
            }
#pragma unroll
            for (int mt = 0; mt < 2; mt++)
#pragma unroll
                for (int nt = 0; nt < 4; nt++) {
                    mma_bf16(pacc[mt][nt], ahi[mt], bf2[nt]);
                    if (sp == 0) mma_bf16(pacc[mt][nt], alo[mt], bf2[nt]);
                }
        }
        if (pf) {
            float4* dst = (float4*)u16b + ((((cc + 1) & 1) ? U_PB1 : U_PB0) >> 3);
#pragma unroll
            for (int i = 0; i < 4; i++) dst[t + i * 256] = tp[i];
        }
        __syncthreads();
    }

    /* ---- epilogue: direct fragment stores (+bias) ---- */
#pragma unroll
    for (int mt = 0; mt < 2; mt++)
#pragma unroll
        for (int nt = 0; nt < 4; nt++)
#pragma unroll
            for (int rh = 0; rh < 2; rh++) {
                int row = wm * 32 + mt * 16 + (l >> 2) + rh * 8;
                if (row < NT) {
                    int col = wn * 32 + nt * 8 + cbase;
                    float2 v;
                    v.x = pacc[mt][nt][rh * 2]     + __ldg(proj_b + col);
                    v.y = pacc[mt][nt][rh * 2 + 1] + __ldg(proj_b + col + 1);
                    *(float2*)&out[base + row * CD + col] = v;
                }
            }
}

extern "C" void kernel_launch(void* const* d_in, const int* in_sizes, int n_in,
                              void* d_out, int out_size) {
    const float* x      = (const float*)d_in[0];
    const float* mask   = (const float*)d_in[1];
    const float* qkv_w  = (const float*)d_in[2];
    const float* qkv_b  = (const float*)d_in[3];
    const float* proj_w = (const float*)d_in[4];
    const float* proj_b = (const float*)d_in[5];
    const float* bt     = (const float*)d_in[6];
    float* out = (float*)d_out;

    int B  = in_sizes[0] / (NT * CD);     /* 16384 */
    int nW = in_sizes[1] / (NT * NT);     /* 1024 */

    prep_w<<<96, 512>>>(qkv_w, proj_w);

    cudaFuncSetAttribute(win_attn_mma,
                         cudaFuncAttributeMaxDynamicSharedMemorySize, SMEM_BYTES);
    win_attn_mma<<<B, 256, SMEM_BYTES>>>(x, mask, qkv_b, proj_b, bt, out, nW);
}

// round 15
// speedup vs baseline: 2.0575x; 1.2777x over previous
#include <cuda_runtime.h>
#include <cuda_bf16.h>
#include <cstdint>

#define NT 49
#define CD 128

/* u16 indices into shared memory */
#define U_Q    0u        /* x-A split [2][64][128] (16384) -> Q blocks overlay (15680) */
#define U_K    16384u    /* K blocks (15680) -> proj-A split [2][64][128] overlay */
#define U_PA   16384u
#define U_V    32768u    /* V row-major [8 blk][64][40] = 20480 -> end 53248 */
#define RPI_BYTE 106496  /* u8 rpi [2401] */
#define SMEM_BYTES 108928

#define QK_BLK 1960u     /* (h*2+sp) block stride for Q/K: 49 rows x 40 */
#define V_BLK  2560u     /* 64 rows x 40 */

/* weights pre-packed as mma B-fragments:
   g_qkvw: [np2][n16 12][k16 8][sp2][lane32][4 u32]  (u16 idx: ((((np*12+n16)*8+k16)*2+sp)*32+lane)*8) */
__device__ __align__(16) uint16_t g_qkvw[98304];
__device__ __align__(16) uint16_t g_projw[32768]; /* [n16 8][k16 8][sp2][lane32][4 u32] */

__device__ __forceinline__ uint32_t smem_u32(const void* p) {
    uint32_t a;
    asm("{ .reg .u64 t; cvta.to.shared.u64 t, %1; cvt.u32.u64 %0, t; }" : "=r"(a) : "l"(p));
    return a;
}
__device__ __forceinline__ void ldsm4(uint32_t* r, uint32_t a) {
    asm volatile("ldmatrix.sync.aligned.m8n8.x4.shared.b16 {%0,%1,%2,%3}, [%4];"
        : "=r"(r[0]), "=r"(r[1]), "=r"(r[2]), "=r"(r[3]) : "r"(a));
}
__device__ __forceinline__ void ldsm4t(uint32_t* r, uint32_t a) {
    asm volatile("ldmatrix.sync.aligned.m8n8.x4.trans.shared.b16 {%0,%1,%2,%3}, [%4];"
        : "=r"(r[0]), "=r"(r[1]), "=r"(r[2]), "=r"(r[3]) : "r"(a));
}
__device__ __forceinline__ void mma_bf16(float* d, const uint32_t* a, const uint32_t* b) {
    asm volatile("mma.sync.aligned.m16n8k16.row.col.f32.bf16.bf16.f32 "
        "{%0,%1,%2,%3}, {%4,%5,%6,%7}, {%8,%9}, {%0,%1,%2,%3};"
        : "+f"(d[0]), "+f"(d[1]), "+f"(d[2]), "+f"(d[3])
        : "r"(a[0]), "r"(a[1]), "r"(a[2]), "r"(a[3]), "r"(b[0]), "r"(b[1]));
}
__device__ __forceinline__ uint32_t pack_hi(float a, float b) {
    __nv_bfloat16 h0 = __float2bfloat16_rn(a), h1 = __float2bfloat16_rn(b);
    return (uint32_t)__bfloat16_as_ushort(h0) | ((uint32_t)__bfloat16_as_ushort(h1) << 16);
}
__device__ __forceinline__ uint32_t pack_lo(float a, float b) {
    __nv_bfloat16 h0 = __float2bfloat16_rn(a), h1 = __float2bfloat16_rn(b);
    float l0 = a - __bfloat162float(h0), l1 = b - __bfloat162float(h1);
    return (uint32_t)__bfloat16_as_ushort(__float2bfloat16_rn(l0)) |
           ((uint32_t)__bfloat16_as_ushort(__float2bfloat16_rn(l1)) << 16);
}

/* ---- prologue: split weights into bf16 hi/lo packed as mma B-fragments ---- */
__global__ void prep_w(const float* __restrict__ qkv_w, const float* __restrict__ proj_w) {
    int i = blockIdx.x * blockDim.x + threadIdx.x;
    if (i < 384 * 128) {
        int n0 = i >> 7, kl = i & 127;
        float f = qkv_w[i];
        __nv_bfloat16 h = __float2bfloat16_rn(f);
        __nv_bfloat16 lo = __float2bfloat16_rn(f - __bfloat162float(h));
        /* column permutation: np0 = K(128-255)+V(256-319); np1 = Q(0-127)+V(320-383) */
        int np, nl;
        if (n0 >= 128 && n0 < 320) { np = 0; nl = n0 - 128; }
        else if (n0 < 128)         { np = 1; nl = n0; }
        else                       { np = 1; nl = n0 - 192; }
        int n16 = nl >> 4, nh8 = (nl >> 3) & 1, nin8 = nl & 7;
        int k16 = kl >> 4, km = kl & 15;
        int lane = nin8 * 4 + ((km & 7) >> 1);
        int r = nh8 * 2 + (km >> 3);
        int base = ((((np * 12 + n16) * 8 + k16) * 2 + 0) * 32 + lane) * 8 + r * 2 + (km & 1);
        g_qkvw[base]       = __bfloat16_as_ushort(h);
        g_qkvw[base + 256] = __bfloat16_as_ushort(lo);   /* sp stride = 32*8 */
    }
    if (i < 128 * 128) {
        int n = i >> 7, kl = i & 127;
        float f = proj_w[i];
        __nv_bfloat16 h = __float2bfloat16_rn(f);
        __nv_bfloat16 lo = __float2bfloat16_rn(f - __bfloat162float(h));
        int n16 = n >> 4, nh8 = (n >> 3) & 1, nin8 = n & 7;
        int k16 = kl >> 4, km = kl & 15;
        int lane = nin8 * 4 + ((km & 7) >> 1);
        int r = nh8 * 2 + (km >> 3);
        int base = (((n16 * 8 + k16) * 2 + 0) * 32 + lane) * 8 + r * 2 + (km & 1);
        g_projw[base]       = __bfloat16_as_ushort(h);
        g_projw[base + 256] = __bfloat16_as_ushort(lo);
    }
}

/* ---- main fused kernel: 256 threads, 2 CTAs/SM ---- */
__global__ __launch_bounds__(256, 2)
void win_attn_mma(const float* __restrict__ x,
                  const float* __restrict__ mask,
                  const float* __restrict__ qkv_b,
                  const float* __restrict__ proj_b,
                  const float* __restrict__ bt,
                  float* __restrict__ out,
                  int nW)
{
    extern __shared__ float sm[];
    uint16_t* u16b = (uint16_t*)sm;
    const int t = threadIdx.x;
    const int w = blockIdx.x;
    const long base = (long)w * (NT * CD);
    const int tn = t & 31, tm = t >> 5;   /* 8 warps */
    const uint32_t smb = smem_u32(sm);

    /* ---- stage x -> A split (swizzled); rpi table ---- */
    for (int idx = t; idx < NT * CD; idx += 256) {
        int r = idx >> 7, k = idx & 127;
        float f = x[base + idx];
        __nv_bfloat16 h = __float2bfloat16_rn(f);
        __nv_bfloat16 lo = __float2bfloat16_rn(f - __bfloat162float(h));
        int sw = ((k >> 3) ^ (r & 7)) * 8 + (k & 7);
        u16b[r * 128 + sw]        = __bfloat16_as_ushort(h);
        u16b[8192 + r * 128 + sw] = __bfloat16_as_ushort(lo);
    }
    {
        uint8_t* rpw = (uint8_t*)sm + RPI_BYTE;
        for (int idx = t; idx < NT * NT; idx += 256) {
            int i = idx / NT, j = idx - i * NT;
            int yi = i / 7, xi = i - yi * 7;
            int yj = j / 7, xj = j - yj * 7;
            rpw[idx] = (uint8_t)((yi - yj + 6) * 13 + (xi - xj + 6));
        }
    }
    __syncthreads();

    const int l = tn;
    const int wm = tm & 1, wn = tm >> 1;
    const int a_r_off = l & 15;
    const int a_c_off = l >> 4;
    const int b_n_off = (l & 7) + (l >> 4) * 8;
    const int b_c_off = (l >> 3) & 1;
    const float scale = 0.1767766952966369f;

    /* ======== QKV GEMM: two passes (np0=K+V01, np1=Q+V23), B via LDG.128 frags ======== */
    for (int np = 0; np < 2; np++) {
        float dacc[2][6][4];
#pragma unroll
        for (int a = 0; a < 2; a++)
#pragma unroll
            for (int b = 0; b < 6; b++)
#pragma unroll
                for (int c = 0; c < 4; c++) dacc[a][b][c] = 0.f;

#pragma unroll
        for (int kt = 0; kt < 8; kt++) {
            uint32_t ahi[2][4], alo[2][4];
#pragma unroll
            for (int mt = 0; mt < 2; mt++) {
                int r = wm * 32 + mt * 16 + a_r_off;
                int ch = kt * 2 + a_c_off;
                uint32_t ad = smb + (((unsigned)(r * 128) + (unsigned)((ch ^ (r & 7)) << 3)) << 1);
                ldsm4(ahi[mt], ad);
                ldsm4(alo[mt], ad + 16384u);
            }
            uint4 bh[3], bl[3];
#pragma unroll
            for (int p = 0; p < 3; p++) {
                unsigned off = (unsigned)(((((np * 12 + wn * 3 + p) * 8 + kt) * 2) * 32 + l) * 8);
                bh[p] = *(const uint4*)&g_qkvw[off];
                bl[p] = *(const uint4*)&g_qkvw[off + 256];
            }
#pragma unroll
            for (int mt = 0; mt < 2; mt++)
#pragma unroll
                for (int p = 0; p < 3; p++) {
                    uint32_t b0h[2] = { bh[p].x, bh[p].y };
                    uint32_t b1h[2] = { bh[p].z, bh[p].w };
                    uint32_t b0l[2] = { bl[p].x, bl[p].y };
                    uint32_t b1l[2] = { bl[p].z, bl[p].w };
                    mma_bf16(dacc[mt][p * 2],     ahi[mt], b0h);
                    mma_bf16(dacc[mt][p * 2],     ahi[mt], b0l);
                    mma_bf16(dacc[mt][p * 2],     alo[mt], b0h);
                    mma_bf16(dacc[mt][p * 2 + 1], ahi[mt], b1h);
                    mma_bf16(dacc[mt][p * 2 + 1], ahi[mt], b1l);
                    mma_bf16(dacc[mt][p * 2 + 1], alo[mt], b1h);
                }
        }
        if (np == 1) __syncthreads();   /* all x-A reads done before Q overlays x */

        /* ---- epilogue: fragments -> K/V01 (np0) or Q/V23 (np1), split-bf16 ---- */
        int r0e = wm * 32 + (l >> 2);
#pragma unroll
        for (int mt = 0; mt < 2; mt++)
#pragma unroll
            for (int nt = 0; nt < 6; nt++)
#pragma unroll
                for (int rh = 0; rh < 2; rh++) {
                    int row = r0e + mt * 16 + rh * 8;
                    if (row >= NT) continue;
                    int c = wn * 48 + nt * 8 + (l & 3) * 2;
                    int ob = np ? ((c < 128) ? c : 192 + c) : 128 + c;
                    float v0 = dacc[mt][nt][rh * 2]     + __ldg(qkv_b + ob);
                    float v1 = dacc[mt][nt][rh * 2 + 1] + __ldg(qkv_b + ob + 1);
                    if (c < 128 && np == 1) {          /* Q (scaled) */
                        v0 *= scale; v1 *= scale;
                        int h = c >> 5, dh = c & 31;
                        uint32_t i0 = U_Q + (unsigned)(h * 2) * QK_BLK + (unsigned)(row * 40 + dh);
                        *(uint32_t*)&u16b[i0]          = pack_hi(v0, v1);
                        *(uint32_t*)&u16b[i0 + QK_BLK] = pack_lo(v0, v1);
                    } else if (c < 128) {              /* K */
                        int h = c >> 5, dh = c & 31;
                        uint32_t i0 = U_K + (unsigned)(h * 2) * QK_BLK + (unsigned)(row * 40 + dh);
                        *(uint32_t*)&u16b[i0]          = pack_hi(v0, v1);
                        *(uint32_t*)&u16b[i0 + QK_BLK] = pack_lo(v0, v1);
                    } else {                           /* V row-major [j=token][dh] */
                        int h = np * 2 + ((c - 128) >> 5);
                        int dh = (c - 128) & 31;
                        uint32_t vb = U_V + (unsigned)(h * 2) * V_BLK + (unsigned)(row * 40 + dh);
                        *(uint32_t*)&u16b[vb]         = pack_hi(v0, v1);
                        *(uint32_t*)&u16b[vb + V_BLK] = pack_lo(v0, v1);
                    }
                }
    }
    /* zero V pad rows 49..63, all 8 blocks */
    for (int i = t; i < 1920; i += 256) {
        int blk = i / 240, rem = i - blk * 240;
        int rr = rem >> 4, dhp = rem & 15;
        *(uint32_t*)&u16b[U_V + (unsigned)blk * V_BLK + (unsigned)((49 + rr) * 40 + dhp * 2)] = 0u;
    }
    __syncthreads();

    /* ======== attention, register-resident: 8 warps = 4 heads x 2 m-halves ======== */
    const float* mrow = mask + (long)(w % nW) * (NT * NT);
    const uint8_t* rp = (const uint8_t*)sm + RPI_BYTE;
    const int h = tm >> 1, half = tm & 1;
    const int cbase = (l & 3) * 2;

    float oacc[2][4][4];
#pragma unroll
    for (int a = 0; a < 2; a++)
#pragma unroll
        for (int b = 0; b < 4; b++)
#pragma unroll
            for (int c = 0; c < 4; c++) oacc[a][b][c] = 0.f;

#pragma unroll
    for (int s2 = 0; s2 < 2; s2++) {
        const int mt = half * 2 + s2;
        const int r0 = mt * 16 + (l >> 2);
        const int r1 = r0 + 8;

        float sacc[8][4];
#pragma unroll
        for (int a = 0; a < 8; a++)
#pragma unroll
            for (int c = 0; c < 4; c++) sacc[a][c] = 0.f;

#pragma unroll
        for (int kk = 0; kk < 2; kk++) {
            uint32_t aq[2][4];
#pragma unroll
            for (int sp = 0; sp < 2; sp++)
                ldsm4(aq[sp], smb + ((U_Q + (unsigned)(h * 2 + sp) * QK_BLK +
                    (unsigned)((mt * 16 + a_r_off) * 40 + (kk * 2 + a_c_off) * 8)) << 1));
            uint32_t bk[8][2][2];
#pragma unroll
            for (int g = 0; g < 4; g++)
#pragma unroll
                for (int sp = 0; sp < 2; sp++) {
                    uint32_t r4[4];
                    ldsm4(r4, smb + ((U_K + (unsigned)(h * 2 + sp) * QK_BLK +
                        (unsigned)((g * 16 + b_n_off) * 40 + (kk * 2 + b_c_off) * 8)) << 1));
                    bk[g * 2][sp][0] = r4[0]; bk[g * 2][sp][1] = r4[1];
                    bk[g * 2 + 1][sp][0] = r4[2]; bk[g * 2 + 1][sp][1] = r4[3];
                }
#pragma unroll
            for (int nt = 0; nt < 8; nt++) {
                mma_bf16(sacc[nt], aq[0], bk[nt][0]);
                mma_bf16(sacc[nt], aq[0], bk[nt][1]);
                mma_bf16(sacc[nt], aq[1], bk[nt][0]);
            }
        }

        /* softmax in registers (+bias via __ldg +mask) */
        {
            int r0c = (r0 < NT) ? r0 : (NT - 1);
            int r1c = (r1 < NT) ? r1 : (NT - 1);
            float m0 = -1e30f, m1 = -1e30f;
#pragma unroll
            for (int nt = 0; nt < 8; nt++)
#pragma unroll
                for (int j = 0; j < 2; j++) {
                    int c = nt * 8 + cbase + j;
                    if (c < NT) {
                        float bi0 = __ldg(bt + rp[r0c * NT + c] * 4 + h);
                        float bi1 = __ldg(bt + rp[r1c * NT + c] * 4 + h);
                        float mk0 = (r0 < NT) ? mrow[r0 * NT + c] : 0.f;
                        float mk1 = (r1 < NT) ? mrow[r1 * NT + c] : 0.f;
                        sacc[nt][j]     += bi0 + mk0;
                        sacc[nt][2 + j] += bi1 + mk1;
                    } else {
                        sacc[nt][j] = -1e30f;
                        sacc[nt][2 + j] = -1e30f;
                    }
                    m0 = fmaxf(m0, sacc[nt][j]);
                    m1 = fmaxf(m1, sacc[nt][2 + j]);
                }
            m0 = fmaxf(m0, __shfl_xor_sync(0xffffffffu, m0, 1));
            m0 = fmaxf(m0, __shfl_xor_sync(0xffffffffu, m0, 2));
            m1 = fmaxf(m1, __shfl_xor_sync(0xffffffffu, m1, 1));
            m1 = fmaxf(m1, __shfl_xor_sync(0xffffffffu, m1, 2));
            float s0 = 0.f, s1 = 0.f;
#pragma unroll
            for (int nt = 0; nt < 8; nt++)
#pragma unroll
                for (int j = 0; j < 2; j++) {
                    float e0 = __expf(sacc[nt][j] - m0);
                    float e1 = __expf(sacc[nt][2 + j] - m1);
                    sacc[nt][j] = e0; sacc[nt][2 + j] = e1;
                    s0 += e0; s1 += e1;
                }
            s0 += __shfl_xor_sync(0xffffffffu, s0, 1);
            s0 += __shfl_xor_sync(0xffffffffu, s0, 2);
            s1 += __shfl_xor_sync(0xffffffffu, s1, 1);
            s1 += __shfl_xor_sync(0xffffffffu, s1, 2);
            float i0 = 1.f / s0, i1 = 1.f / s1;
#pragma unroll
            for (int nt = 0; nt < 8; nt++)
#pragma unroll
                for (int j = 0; j < 2; j++) { sacc[nt][j] *= i0; sacc[nt][2 + j] *= i1; }
        }

        /* PV: P straight from registers; V via ldmatrix.trans on row-major V */
#pragma unroll
        for (int kt = 0; kt < 4; kt++) {
            uint32_t ah[4], al[4];
            ah[0] = pack_hi(sacc[2 * kt][0], sacc[2 * kt][1]);
            ah[1] = pack_hi(sacc[2 * kt][2], sacc[2 * kt][3]);
            ah[2] = pack_hi(sacc[2 * kt + 1][0], sacc[2 * kt + 1][1]);
            ah[3] = pack_hi(sacc[2 * kt + 1][2], sacc[2 * kt + 1][3]);
            al[0] = pack_lo(sacc[2 * kt][0], sacc[2 * kt][1]);
            al[1] = pack_lo(sacc[2 * kt][2], sacc[2 * kt][3]);
            al[2] = pack_lo(sacc[2 * kt + 1][0], sacc[2 * kt + 1][1]);
            al[3] = pack_lo(sacc[2 * kt + 1][2], sacc[2 * kt + 1][3]);
            uint32_t bv[4][2][2];
#pragma unroll
            for (int g = 0; g < 2; g++)
#pragma unroll
                for (int sp = 0; sp < 2; sp++) {
                    uint32_t r4[4];
                    ldsm4t(r4, smb + ((U_V + (unsigned)(h * 2 + sp) * V_BLK +
                        (unsigned)((kt * 16 + a_r_off) * 40 + g * 16 + a_c_off * 8)) << 1));
                    bv[g * 2][sp][0] = r4[0]; bv[g * 2][sp][1] = r4[1];
                    bv[g * 2 + 1][sp][0] = r4[2]; bv[g * 2 + 1][sp][1] = r4[3];
                }
#pragma unroll
            for (int n = 0; n < 4; n++) {
                mma_bf16(oacc[s2][n], ah, bv[n][0]);
                mma_bf16(oacc[s2][n], ah, bv[n][1]);
                mma_bf16(oacc[s2][n], al, bv[n][0]);
            }
        }
    }
    __syncthreads();   /* all Q/K/V reads done */

    /* ---- O fragments -> proj-A split (overlays K region) ---- */
#pragma unroll
    for (int s2 = 0; s2 < 2; s2++)
#pragma unroll
        for (int n = 0; n < 4; n++)
#pragma unroll
            for (int rh = 0; rh < 2; rh++) {
                int row = (half * 2 + s2) * 16 + (l >> 2) + rh * 8;
                int c = h * 32 + n * 8 + cbase;
                int sw = ((c >> 3) ^ (row & 7)) * 8 + (c & 7);
                *(uint32_t*)&u16b[U_PA + (unsigned)(row * 128 + sw)] =
                    pack_hi(oacc[s2][n][rh * 2], oacc[s2][n][rh * 2 + 1]);
                *(uint32_t*)&u16b[U_PA + 8192u + (unsigned)(row * 128 + sw)] =
                    pack_lo(oacc[s2][n][rh * 2], oacc[s2][n][rh * 2 + 1]);
            }
    __syncthreads();

    /* ======== proj GEMM: D[64x128] = O @ proj_w^T, B via LDG.128 frags ======== */
    float pacc[2][4][4];
#pragma unroll
    for (int a = 0; a < 2; a++)
#pragma unroll
        for (int b = 0; b < 4; b++)
#pragma unroll
            for (int c = 0; c < 4; c++) pacc[a][b][c] = 0.f;

#pragma unroll
    for (int kt = 0; kt < 8; kt++) {
        uint32_t ahi[2][4], alo[2][4];
#pragma unroll
        for (int mt2 = 0; mt2 < 2; mt2++) {
            int r = wm * 32 + mt2 * 16 + a_r_off;
            int ch = kt * 2 + a_c_off;
            uint32_t ad = smb + ((U_PA + (unsigned)(r * 128) + (unsigned)((ch ^ (r & 7)) << 3)) << 1);
            ldsm4(ahi[mt2], ad);
            ldsm4(alo[mt2], ad + 16384u);
        }
        uint4 bh[2], bl[2];
#pragma unroll
        for (int p2 = 0; p2 < 2; p2++) {
            unsigned off = (unsigned)((((wn * 2 + p2) * 8 + kt) * 2 * 32 + l) * 8);
            bh[p2] = *(const uint4*)&g_projw[off];
            bl[p2] = *(const uint4*)&g_projw[off + 256];
        }
#pragma unroll
        for (int mt2 = 0; mt2 < 2; mt2++)
#pragma unroll
            for (int p2 = 0; p2 < 2; p2++) {
                uint32_t b0h[2] = { bh[p2].x, bh[p2].y };
                uint32_t b1h[2] = { bh[p2].z, bh[p2].w };
                uint32_t b0l[2] = { bl[p2].x, bl[p2].y };
                uint32_t b1l[2] = { bl[p2].z, bl[p2].w };
                mma_bf16(pacc[mt2][p2 * 2],     ahi[mt2], b0h);
                mma_bf16(pacc[mt2][p2 * 2],     ahi[mt2], b0l);
                mma_bf16(pacc[mt2][p2 * 2],     alo[mt2], b0h);
                mma_bf16(pacc[mt2][p2 * 2 + 1], ahi[mt2], b1h);
                mma_bf16(pacc[mt2][p2 * 2 + 1], ahi[mt2], b1l);
                mma_bf16(pacc[mt2][p2 * 2 + 1], alo[mt2], b1h);
            }
    }

    /* ---- epilogue: direct fragment stores (+bias) ---- */
#pragma unroll
    for (int mt2 = 0; mt2 < 2; mt2++)
#pragma unroll
        for (int nt = 0; nt < 4; nt++)
#pragma unroll
            for (int rh = 0; rh < 2; rh++) {
                int row = wm * 32 + mt2 * 16 + (l >> 2) + rh * 8;
                if (row < NT) {
                    int col = wn * 32 + nt * 8 + cbase;
                    float2 v;
                    v.x = pacc[mt2][nt][rh * 2]     + __ldg(proj_b + col);
                    v.y = pacc[mt2][nt][rh * 2 + 1] + __ldg(proj_b + col + 1);
                    *(float2*)&out[base + row * CD + col] = v;
                }
            }
}

extern "C" void kernel_launch(void* const* d_in, const int* in_sizes, int n_in,
                              void* d_out, int out_size) {
    const float* x      = (const float*)d_in[0];
    const float* mask   = (const float*)d_in[1];
    const float* qkv_w  = (const float*)d_in[2];
    const float* qkv_b  = (const float*)d_in[3];
    const float* proj_w = (const float*)d_in[4];
    const float* proj_b = (const float*)d_in[5];
    const float* bt     = (const float*)d_in[6];
    float* out = (float*)d_out;

    int B  = in_sizes[0] / (NT * CD);     /* 16384 */
    int nW = in_sizes[1] / (NT * NT);     /* 1024 */

    prep_w<<<96, 512>>>(qkv_w, proj_w);

    cudaFuncSetAttribute(win_attn_mma,
                         cudaFuncAttributeMaxDynamicSharedMemorySize, SMEM_BYTES);
    win_attn_mma<<<B, 256, SMEM_BYTES>>>(x, mask, qkv_b, proj_b, bt, out, nW);
}

// round 16
// speedup vs baseline: 2.1017x; 1.0215x over previous
#include <cuda_runtime.h>
#include <cuda_bf16.h>
#include <cstdint>

#define NT 49
#define CD 128

/* u16 indices into shared memory */
#define U_Q    0u        /* x-A split [2][64][128] (16384) -> Q blocks overlay (15680) */
#define U_K    16384u    /* K blocks (15680) -> proj-A split [2][64][128] overlay */
#define U_PA   16384u
#define U_V    32768u    /* V row-major [8 blk][64][40] = 20480 -> end 53248 */
#define RPI_BYTE 106496  /* u8 rpi [2401] */
#define SMEM_BYTES 108928

#define QK_BLK 1960u     /* (h*2+sp) block stride for Q/K: 49 rows x 40 */
#define V_BLK  2560u     /* 64 rows x 40 */

/* weights pre-packed as mma B-fragments:
   g_qkvw: [np2][n16 12][k16 8][sp2][lane32][4 u32] */
__device__ __align__(16) uint16_t g_qkvw[98304];
__device__ __align__(16) uint16_t g_projw[32768]; /* [n16 8][k16 8][sp2][lane32][4 u32] */

__device__ __forceinline__ uint32_t smem_u32(const void* p) {
    uint32_t a;
    asm("{ .reg .u64 t; cvta.to.shared.u64 t, %1; cvt.u32.u64 %0, t; }" : "=r"(a) : "l"(p));
    return a;
}
__device__ __forceinline__ void ldsm4(uint32_t* r, uint32_t a) {
    asm volatile("ldmatrix.sync.aligned.m8n8.x4.shared.b16 {%0,%1,%2,%3}, [%4];"
        : "=r"(r[0]), "=r"(r[1]), "=r"(r[2]), "=r"(r[3]) : "r"(a));
}
__device__ __forceinline__ void ldsm4t(uint32_t* r, uint32_t a) {
    asm volatile("ldmatrix.sync.aligned.m8n8.x4.trans.shared.b16 {%0,%1,%2,%3}, [%4];"
        : "=r"(r[0]), "=r"(r[1]), "=r"(r[2]), "=r"(r[3]) : "r"(a));
}
__device__ __forceinline__ void mma_bf16(float* d, const uint32_t* a, const uint32_t* b) {
    asm volatile("mma.sync.aligned.m16n8k16.row.col.f32.bf16.bf16.f32 "
        "{%0,%1,%2,%3}, {%4,%5,%6,%7}, {%8,%9}, {%0,%1,%2,%3};"
        : "+f"(d[0]), "+f"(d[1]), "+f"(d[2]), "+f"(d[3])
        : "r"(a[0]), "r"(a[1]), "r"(a[2]), "r"(a[3]), "r"(b[0]), "r"(b[1]));
}
__device__ __forceinline__ uint32_t pack_hi(float a, float b) {
    __nv_bfloat16 h0 = __float2bfloat16_rn(a), h1 = __float2bfloat16_rn(b);
    return (uint32_t)__bfloat16_as_ushort(h0) | ((uint32_t)__bfloat16_as_ushort(h1) << 16);
}
__device__ __forceinline__ uint32_t pack_lo(float a, float b) {
    __nv_bfloat16 h0 = __float2bfloat16_rn(a), h1 = __float2bfloat16_rn(b);
    float l0 = a - __bfloat162float(h0), l1 = b - __bfloat162float(h1);
    return (uint32_t)__bfloat16_as_ushort(__float2bfloat16_rn(l0)) |
           ((uint32_t)__bfloat16_as_ushort(__float2bfloat16_rn(l1)) << 16);
}

/* ---- prologue: split weights into bf16 hi/lo packed as mma B-fragments ---- */
__global__ void prep_w(const float* __restrict__ qkv_w, const float* __restrict__ proj_w) {
    int i = blockIdx.x * blockDim.x + threadIdx.x;
    if (i < 384 * 128) {
        int n0 = i >> 7, kl = i & 127;
        float f = qkv_w[i];
        __nv_bfloat16 h = __float2bfloat16_rn(f);
        __nv_bfloat16 lo = __float2bfloat16_rn(f - __bfloat162float(h));
        /* column permutation: np0 = K(128-255)+V(256-319); np1 = Q(0-127)+V(320-383) */
        int np, nl;
        if (n0 >= 128 && n0 < 320) { np = 0; nl = n0 - 128; }
        else if (n0 < 128)         { np = 1; nl = n0; }
        else                       { np = 1; nl = n0 - 192; }
        int n16 = nl >> 4, nh8 = (nl >> 3) & 1, nin8 = nl & 7;
        int k16 = kl >> 4, km = kl & 15;
        int lane = nin8 * 4 + ((km & 7) >> 1);
        int r = nh8 * 2 + (km >> 3);
        int base = ((((np * 12 + n16) * 8 + k16) * 2 + 0) * 32 + lane) * 8 + r * 2 + (km & 1);
        g_qkvw[base]       = __bfloat16_as_ushort(h);
        g_qkvw[base + 256] = __bfloat16_as_ushort(lo);   /* sp stride = 32*8 */
    }
    if (i < 128 * 128) {
        int n = i >> 7, kl = i & 127;
        float f = proj_w[i];
        __nv_bfloat16 h = __float2bfloat16_rn(f);
        __nv_bfloat16 lo = __float2bfloat16_rn(f - __bfloat162float(h));
        int n16 = n >> 4, nh8 = (n >> 3) & 1, nin8 = n & 7;
        int k16 = kl >> 4, km = kl & 15;
        int lane = nin8 * 4 + ((km & 7) >> 1);
        int r = nh8 * 2 + (km >> 3);
        int base = (((n16 * 8 + k16) * 2 + 0) * 32 + lane) * 8 + r * 2 + (km & 1);
        g_projw[base]       = __bfloat16_as_ushort(h);
        g_projw[base + 256] = __bfloat16_as_ushort(lo);
    }
}

/* ---- main fused kernel: 256 threads, 2 CTAs/SM ---- */
__global__ __launch_bounds__(256, 2)
void win_attn_mma(const float* __restrict__ x,
                  const float* __restrict__ mask,
                  const float* __restrict__ qkv_b,
                  const float* __restrict__ proj_b,
                  const float* __restrict__ bt,
                  float* __restrict__ out,
                  int nW)
{
    extern __shared__ float sm[];
    uint16_t* u16b = (uint16_t*)sm;
    const int t = threadIdx.x;
    const int w = blockIdx.x;
    const long base = (long)w * (NT * CD);
    const int tn = t & 31, tm = t >> 5;   /* 8 warps */
    const uint32_t smb = smem_u32(sm);

    /* ---- stage x -> A split (swizzled); V pad rows; rpi table ---- */
    for (int idx = t; idx < NT * CD; idx += 256) {
        int r = idx >> 7, k = idx & 127;
        float f = x[base + idx];
        __nv_bfloat16 h = __float2bfloat16_rn(f);
        __nv_bfloat16 lo = __float2bfloat16_rn(f - __bfloat162float(h));
        int sw = ((k >> 3) ^ (r & 7)) * 8 + (k & 7);
        u16b[r * 128 + sw]        = __bfloat16_as_ushort(h);
        u16b[8192 + r * 128 + sw] = __bfloat16_as_ushort(lo);
    }
    /* zero V pad rows 49..63, all 8 blocks (region untouched until epilogue) */
    for (int i = t; i < 1920; i += 256) {
        int blk = i / 240, rem = i - blk * 240;
        int rr = rem >> 4, dhp = rem & 15;
        *(uint32_t*)&u16b[U_V + (unsigned)blk * V_BLK + (unsigned)((49 + rr) * 40 + dhp * 2)] = 0u;
    }
    {
        uint8_t* rpw = (uint8_t*)sm + RPI_BYTE;
        for (int idx = t; idx < NT * NT; idx += 256) {
            int i = idx / NT, j = idx - i * NT;
            int yi = i / 7, xi = i - yi * 7;
            int yj = j / 7, xj = j - yj * 7;
            rpw[idx] = (uint8_t)((yi - yj + 6) * 13 + (xi - xj + 6));
        }
    }
    __syncthreads();

    const int l = tn;
    const int wm = tm & 1, wn = tm >> 1;
    const int a_r_off = l & 15;
    const int a_c_off = l >> 4;
    const int b_n_off = (l & 7) + (l >> 4) * 8;
    const int b_c_off = (l >> 3) & 1;
    const float scale = 0.1767766952966369f;

    /* ======== QKV GEMM: two passes (np0=K+V01, np1=Q+V23), B via LDG.128 frags ======== */
    for (int np = 0; np < 2; np++) {
        float dacc[2][6][4];
#pragma unroll
        for (int a = 0; a < 2; a++)
#pragma unroll
            for (int b = 0; b < 6; b++)
#pragma unroll
                for (int c = 0; c < 4; c++) dacc[a][b][c] = 0.f;

#pragma unroll
        for (int kt = 0; kt < 8; kt++) {
            uint4 bh[3], bl[3];
#pragma unroll
            for (int p = 0; p < 3; p++) {
                unsigned off = (unsigned)(((((np * 12 + wn * 3 + p) * 8 + kt) * 2) * 32 + l) * 8);
                bh[p] = __ldg((const uint4*)&g_qkvw[off]);
                bl[p] = __ldg((const uint4*)&g_qkvw[off + 256]);
            }
            uint32_t ahi[2][4], alo[2][4];
#pragma unroll
            for (int mt = 0; mt < 2; mt++) {
                int r = wm * 32 + mt * 16 + a_r_off;
                int ch = kt * 2 + a_c_off;
                uint32_t ad = smb + (((unsigned)(r * 128) + (unsigned)((ch ^ (r & 7)) << 3)) << 1);
                ldsm4(ahi[mt], ad);
                ldsm4(alo[mt], ad + 16384u);
            }
#pragma unroll
            for (int mt = 0; mt < 2; mt++)
#pragma unroll
                for (int p = 0; p < 3; p++) {
                    uint32_t b0h[2] = { bh[p].x, bh[p].y };
                    uint32_t b1h[2] = { bh[p].z, bh[p].w };
                    uint32_t b0l[2] = { bl[p].x, bl[p].y };
                    uint32_t b1l[2] = { bl[p].z, bl[p].w };
                    mma_bf16(dacc[mt][p * 2],     ahi[mt], b0h);
                    mma_bf16(dacc[mt][p * 2],     ahi[mt], b0l);
                    mma_bf16(dacc[mt][p * 2],     alo[mt], b0h);
                    mma_bf16(dacc[mt][p * 2 + 1], ahi[mt], b1h);
                    mma_bf16(dacc[mt][p * 2 + 1], ahi[mt], b1l);
                    mma_bf16(dacc[mt][p * 2 + 1], alo[mt], b1h);
                }
        }
        if (np == 1) __syncthreads();   /* all x-A reads done before Q overlays x */

        /* ---- epilogue: fragments -> K/V01 (np0) or Q/V23 (np1), split-bf16 ---- */
        int r0e = wm * 32 + (l >> 2);
#pragma unroll
        for (int mt = 0; mt < 2; mt++)
#pragma unroll
            for (int nt = 0; nt < 6; nt++)
#pragma unroll
                for (int rh = 0; rh < 2; rh++) {
                    int row = r0e + mt * 16 + rh * 8;
                    if (row >= NT) continue;
                    int c = wn * 48 + nt * 8 + (l & 3) * 2;
                    int ob = np ? ((c < 128) ? c : 192 + c) : 128 + c;
                    float v0 = dacc[mt][nt][rh * 2]     + __ldg(qkv_b + ob);
                    float v1 = dacc[mt][nt][rh * 2 + 1] + __ldg(qkv_b + ob + 1);
                    if (c < 128 && np == 1) {          /* Q (scaled) */
                        v0 *= scale; v1 *= scale;
                        int h = c >> 5, dh = c & 31;
                        uint32_t i0 = U_Q + (unsigned)(h * 2) * QK_BLK + (unsigned)(row * 40 + dh);
                        *(uint32_t*)&u16b[i0]          = pack_hi(v0, v1);
                        *(uint32_t*)&u16b[i0 + QK_BLK] = pack_lo(v0, v1);
                    } else if (c < 128) {              /* K */
                        int h = c >> 5, dh = c & 31;
                        uint32_t i0 = U_K + (unsigned)(h * 2) * QK_BLK + (unsigned)(row * 40 + dh);
                        *(uint32_t*)&u16b[i0]          = pack_hi(v0, v1);
                        *(uint32_t*)&u16b[i0 + QK_BLK] = pack_lo(v0, v1);
                    } else {                           /* V row-major [j=token][dh] */
                        int h = np * 2 + ((c - 128) >> 5);
                        int dh = (c - 128) & 31;
                        uint32_t vb = U_V + (unsigned)(h * 2) * V_BLK + (unsigned)(row * 40 + dh);
                        *(uint32_t*)&u16b[vb]         = pack_hi(v0, v1);
                        *(uint32_t*)&u16b[vb + V_BLK] = pack_lo(v0, v1);
                    }
                }
    }
    __syncthreads();

    /* ======== attention, register-resident, JOINT m-halves: K/V frags loaded once ======== */
    const float* mrow = mask + (long)(w % nW) * (NT * NT);
    const uint8_t* rp = (const uint8_t*)sm + RPI_BYTE;
    const int h = tm >> 1, half = tm & 1;
    const int cbase = (l & 3) * 2;

    /* ---- S = (Q*scale) K^T for BOTH m16 tiles of this warp ---- */
    float sacc[2][8][4];
#pragma unroll
    for (int s2 = 0; s2 < 2; s2++)
#pragma unroll
        for (int a = 0; a < 8; a++)
#pragma unroll
            for (int c = 0; c < 4; c++) sacc[s2][a][c] = 0.f;

#pragma unroll
    for (int kk = 0; kk < 2; kk++) {
        uint32_t aq[2][2][4];
#pragma unroll
        for (int s2 = 0; s2 < 2; s2++)
#pragma unroll
            for (int sp = 0; sp < 2; sp++)
                ldsm4(aq[s2][sp], smb + ((U_Q + (unsigned)(h * 2 + sp) * QK_BLK +
                    (unsigned)(((half * 2 + s2) * 16 + a_r_off) * 40 + (kk * 2 + a_c_off) * 8)) << 1));
#pragma unroll
        for (int g = 0; g < 4; g++) {
            uint32_t bh4[4], bl4[4];
            uint32_t kad = smb + ((U_K + (unsigned)(h * 2) * QK_BLK +
                (unsigned)((g * 16 + b_n_off) * 40 + (kk * 2 + b_c_off) * 8)) << 1);
            ldsm4(bh4, kad);
            ldsm4(bl4, kad + (QK_BLK << 1));
            uint32_t b0h[2] = { bh4[0], bh4[1] }, b1h[2] = { bh4[2], bh4[3] };
            uint32_t b0l[2] = { bl4[0], bl4[1] }, b1l[2] = { bl4[2], bl4[3] };
#pragma unroll
            for (int s2 = 0; s2 < 2; s2++) {
                mma_bf16(sacc[s2][g * 2],     aq[s2][0], b0h);
                mma_bf16(sacc[s2][g * 2],     aq[s2][0], b0l);
                mma_bf16(sacc[s2][g * 2],     aq[s2][1], b0h);
                mma_bf16(sacc[s2][g * 2 + 1], aq[s2][0], b1h);
                mma_bf16(sacc[s2][g * 2 + 1], aq[s2][0], b1l);
                mma_bf16(sacc[s2][g * 2 + 1], aq[s2][1], b1h);
            }
        }
    }

    /* ---- softmax in registers for both halves (+bias via __ldg +mask) ---- */
#pragma unroll
    for (int s2 = 0; s2 < 2; s2++) {
        const int r0 = (half * 2 + s2) * 16 + (l >> 2);
        const int r1 = r0 + 8;
        int r0c = (r0 < NT) ? r0 : (NT - 1);
        int r1c = (r1 < NT) ? r1 : (NT - 1);
        float m0 = -1e30f, m1 = -1e30f;
#pragma unroll
        for (int nt = 0; nt < 8; nt++)
#pragma unroll
            for (int j = 0; j < 2; j++) {
                int c = nt * 8 + cbase + j;
                if (c < NT) {
                    float bi0 = __ldg(bt + rp[r0c * NT + c] * 4 + h);
                    float bi1 = __ldg(bt + rp[r1c * NT + c] * 4 + h);
                    float mk0 = (r0 < NT) ? mrow[r0 * NT + c] : 0.f;
                    float mk1 = (r1 < NT) ? mrow[r1 * NT + c] : 0.f;
                    sacc[s2][nt][j]     += bi0 + mk0;
                    sacc[s2][nt][2 + j] += bi1 + mk1;
                } else {
                    sacc[s2][nt][j] = -1e30f;
                    sacc[s2][nt][2 + j] = -1e30f;
                }
                m0 = fmaxf(m0, sacc[s2][nt][j]);
                m1 = fmaxf(m1, sacc[s2][nt][2 + j]);
            }
        m0 = fmaxf(m0, __shfl_xor_sync(0xffffffffu, m0, 1));
        m0 = fmaxf(m0, __shfl_xor_sync(0xffffffffu, m0, 2));
        m1 = fmaxf(m1, __shfl_xor_sync(0xffffffffu, m1, 1));
        m1 = fmaxf(m1, __shfl_xor_sync(0xffffffffu, m1, 2));
        float s0 = 0.f, s1 = 0.f;
#pragma unroll
        for (int nt = 0; nt < 8; nt++)
#pragma unroll
            for (int j = 0; j < 2; j++) {
                float e0 = __expf(sacc[s2][nt][j] - m0);
                float e1 = __expf(sacc[s2][nt][2 + j] - m1);
                sacc[s2][nt][j] = e0; sacc[s2][nt][2 + j] = e1;
                s0 += e0; s1 += e1;
            }
        s0 += __shfl_xor_sync(0xffffffffu, s0, 1);
        s0 += __shfl_xor_sync(0xffffffffu, s0, 2);
        s1 += __shfl_xor_sync(0xffffffffu, s1, 1);
        s1 += __shfl_xor_sync(0xffffffffu, s1, 2);
        float i0 = 1.f / s0, i1 = 1.f / s1;
#pragma unroll
        for (int nt = 0; nt < 8; nt++)
#pragma unroll
            for (int j = 0; j < 2; j++) { sacc[s2][nt][j] *= i0; sacc[s2][nt][2 + j] *= i1; }
    }

    /* ---- PV for both halves: V frags loaded once per (kt,g) ---- */
    float oacc[2][4][4];
#pragma unroll
    for (int a = 0; a < 2; a++)
#pragma unroll
        for (int b = 0; b < 4; b++)
#pragma unroll
            for (int c = 0; c < 4; c++) oacc[a][b][c] = 0.f;

#pragma unroll
    for (int kt = 0; kt < 4; kt++) {
        uint32_t ah[2][4], al[2][4];
#pragma unroll
        for (int s2 = 0; s2 < 2; s2++) {
            ah[s2][0] = pack_hi(sacc[s2][2 * kt][0], sacc[s2][2 * kt][1]);
            ah[s2][1] = pack_hi(sacc[s2][2 * kt][2], sacc[s2][2 * kt][3]);
            ah[s2][2] = pack_hi(sacc[s2][2 * kt + 1][0], sacc[s2][2 * kt + 1][1]);
            ah[s2][3] = pack_hi(sacc[s2][2 * kt + 1][2], sacc[s2][2 * kt + 1][3]);
            al[s2][0] = pack_lo(sacc[s2][2 * kt][0], sacc[s2][2 * kt][1]);
            al[s2][1] = pack_lo(sacc[s2][2 * kt][2], sacc[s2][2 * kt][3]);
            al[s2][2] = pack_lo(sacc[s2][2 * kt + 1][0], sacc[s2][2 * kt + 1][1]);
            al[s2][3] = pack_lo(sacc[s2][2 * kt + 1][2], sacc[s2][2 * kt + 1][3]);
        }
#pragma unroll
        for (int g = 0; g < 2; g++) {
            uint32_t bh4[4], bl4[4];
            uint32_t vad = smb + ((U_V + (unsigned)(h * 2) * V_BLK +
                (unsigned)((kt * 16 + a_r_off) * 40 + g * 16 + a_c_off * 8)) << 1);
            ldsm4t(bh4, vad);
            ldsm4t(bl4, vad + (V_BLK << 1));
            uint32_t b0h[2] = { bh4[0], bh4[1] }, b1h[2] = { bh4[2], bh4[3] };
            uint32_t b0l[2] = { bl4[0], bl4[1] }, b1l[2] = { bl4[2], bl4[3] };
#pragma unroll
            for (int s2 = 0; s2 < 2; s2++) {
                mma_bf16(oacc[s2][g * 2],     ah[s2], b0h);
                mma_bf16(oacc[s2][g * 2],     ah[s2], b0l);
                mma_bf16(oacc[s2][g * 2],     al[s2], b0h);
                mma_bf16(oacc[s2][g * 2 + 1], ah[s2], b1h);
                mma_bf16(oacc[s2][g * 2 + 1], ah[s2], b1l);
                mma_bf16(oacc[s2][g * 2 + 1], al[s2], b1h);
            }
        }
    }
    __syncthreads();   /* all Q/K/V reads done */

    /* ---- O fragments -> proj-A split (overlays K region) ---- */
#pragma unroll
    for (int s2 = 0; s2 < 2; s2++)
#pragma unroll
        for (int n = 0; n < 4; n++)
#pragma unroll
            for (int rh = 0; rh < 2; rh++) {
                int row = (half * 2 + s2) * 16 + (l >> 2) + rh * 8;
                int c = h * 32 + n * 8 + cbase;
                int sw = ((c >> 3) ^ (row & 7)) * 8 + (c & 7);
                *(uint32_t*)&u16b[U_PA + (unsigned)(row * 128 + sw)] =
                    pack_hi(oacc[s2][n][rh * 2], oacc[s2][n][rh * 2 + 1]);
                *(uint32_t*)&u16b[U_PA + 8192u + (unsigned)(row * 128 + sw)] =
                    pack_lo(oacc[s2][n][rh * 2], oacc[s2][n][rh * 2 + 1]);
            }
    __syncthreads();

    /* ======== proj GEMM: D[64x128] = O @ proj_w^T, B via LDG.128 frags ======== */
    float pacc[2][4][4];
#pragma unroll
    for (int a = 0; a < 2; a++)
#pragma unroll
        for (int b = 0; b < 4; b++)
#pragma unroll
            for (int c = 0; c < 4; c++) pacc[a][b][c] = 0.f;

#pragma unroll
    for (int kt = 0; kt < 8; kt++) {
        uint4 bh[2], bl[2];
#pragma unroll
        for (int p2 = 0; p2 < 2; p2++) {
            unsigned off = (unsigned)((((wn * 2 + p2) * 8 + kt) * 2 * 32 + l) * 8);
            bh[p2] = __ldg((const uint4*)&g_projw[off]);
            bl[p2] = __ldg((const uint4*)&g_projw[off + 256]);
        }
        uint32_t ahi[2][4], alo[2][4];
#pragma unroll
        for (int mt2 = 0; mt2 < 2; mt2++) {
            int r = wm * 32 + mt2 * 16 + a_r_off;
            int ch = kt * 2 + a_c_off;
            uint32_t ad = smb + ((U_PA + (unsigned)(r * 128) + (unsigned)((ch ^ (r & 7)) << 3)) << 1);
            ldsm4(ahi[mt2], ad);
            ldsm4(alo[mt2], ad + 16384u);
        }
#pragma unroll
        for (int mt2 = 0; mt2 < 2; mt2++)
#pragma unroll
            for (int p2 = 0; p2 < 2; p2++) {
                uint32_t b0h[2] = { bh[p2].x, bh[p2].y };
                uint32_t b1h[2] = { bh[p2].z, bh[p2].w };
                uint32_t b0l[2] = { bl[p2].x, bl[p2].y };
                uint32_t b1l[2] = { bl[p2].z, bl[p2].w };
                mma_bf16(pacc[mt2][p2 * 2],     ahi[mt2], b0h);
                mma_bf16(pacc[mt2][p2 * 2],     ahi[mt2], b0l);
                mma_bf16(pacc[mt2][p2 * 2],     alo[mt2], b0h);
                mma_bf16(pacc[mt2][p2 * 2 + 1], ahi[mt2], b1h);
                mma_bf16(pacc[mt2][p2 * 2 + 1], ahi[mt2], b1l);
                mma_bf16(pacc[mt2][p2 * 2 + 1], alo[mt2], b1h);
            }
    }

    /* ---- epilogue: direct fragment stores (+bias) ---- */
#pragma unroll
    for (int mt2 = 0; mt2 < 2; mt2++)
#pragma unroll
        for (int nt = 0; nt < 4; nt++)
#pragma unroll
            for (int rh = 0; rh < 2; rh++) {
                int row = wm * 32 + mt2 * 16 + (l >> 2) + rh * 8;
                if (row < NT) {
                    int col = wn * 32 + nt * 8 + cbase;
                    float2 v;
                    v.x = pacc[mt2][nt][rh * 2]     + __ldg(proj_b + col);
                    v.y = pacc[mt2][nt][rh * 2 + 1] + __ldg(proj_b + col + 1);
                    *(float2*)&out[base + row * CD + col] = v;
                }
            }
}

extern "C" void kernel_launch(void* const* d_in, const int* in_sizes, int n_in,
                              void* d_out, int out_size) {
    const float* x      = (const float*)d_in[0];
    const float* mask   = (const float*)d_in[1];
    const float* qkv_w  = (const float*)d_in[2];
    const float* qkv_b  = (const float*)d_in[3];
    const float* proj_w = (const float*)d_in[4];
    const float* proj_b = (const float*)d_in[5];
    const float* bt     = (const float*)d_in[6];
    float* out = (float*)d_out;

    int B  = in_sizes[0] / (NT * CD);     /* 16384 */
    int nW = in_sizes[1] / (NT * NT);     /* 1024 */

    prep_w<<<96, 512>>>(qkv_w, proj_w);

    cudaFuncSetAttribute(win_attn_mma,
                         cudaFuncAttributeMaxDynamicSharedMemorySize, SMEM_BYTES);
    win_attn_mma<<<B, 256, SMEM_BYTES>>>(x, mask, qkv_b, proj_b, bt, out, nW);
}

// round 17
// speedup vs baseline: 2.1867x; 1.0404x over previous
#include <cuda_runtime.h>
#include <cuda_bf16.h>
#include <cstdint>

#define NT 49
#define CD 128

/* u16 indices / layout:
   U_QI  : x-A split [2][64][128] (16384 u16) -> Q A-frag image overlay
           Q img: frag idx (((h*2+sp)*2+kk)*4 + mtile), 256 u16/frag
   U_KI  : K B-frag image (16384 u16): (((h*2+sp)*2+kk)*8 + tokgrp), 128 u16/frag
           -> O A-frag image overlay: ((sp*8+kt)*4 + mtile), 256 u16/frag
   U_V   : V row-major [8 blk][64][40] (20480 u16)
   F_BT  : bias table 676 f32 (float idx)
*/
#define U_QI 0u
#define U_KI 16384u
#define U_V  32768u
#define F_BT 26624
#define RPI_BYTE 109200
#define SMEM_BYTES 111616

#define V_BLK 2560u

/* weights pre-packed as mma B-fragments (unchanged from R15/16) */
__device__ __align__(16) uint16_t g_qkvw[98304];
__device__ __align__(16) uint16_t g_projw[32768];

__device__ __forceinline__ uint32_t smem_u32(const void* p) {
    uint32_t a;
    asm("{ .reg .u64 t; cvta.to.shared.u64 t, %1; cvt.u32.u64 %0, t; }" : "=r"(a) : "l"(p));
    return a;
}
__device__ __forceinline__ void ldsm4(uint32_t* r, uint32_t a) {
    asm volatile("ldmatrix.sync.aligned.m8n8.x4.shared.b16 {%0,%1,%2,%3}, [%4];"
        : "=r"(r[0]), "=r"(r[1]), "=r"(r[2]), "=r"(r[3]) : "r"(a));
}
__device__ __forceinline__ void ldsm4t(uint32_t* r, uint32_t a) {
    asm volatile("ldmatrix.sync.aligned.m8n8.x4.trans.shared.b16 {%0,%1,%2,%3}, [%4];"
        : "=r"(r[0]), "=r"(r[1]), "=r"(r[2]), "=r"(r[3]) : "r"(a));
}
__device__ __forceinline__ void lds128(uint32_t* r, uint32_t a) {
    asm volatile("ld.shared.v4.b32 {%0,%1,%2,%3}, [%4];"
        : "=r"(r[0]), "=r"(r[1]), "=r"(r[2]), "=r"(r[3]) : "r"(a));
}
__device__ __forceinline__ void lds64(uint32_t* r, uint32_t a) {
    asm volatile("ld.shared.v2.b32 {%0,%1}, [%2];" : "=r"(r[0]), "=r"(r[1]) : "r"(a));
}
__device__ __forceinline__ void sts128(uint32_t a, uint32_t v0, uint32_t v1, uint32_t v2, uint32_t v3) {
    asm volatile("st.shared.v4.b32 [%0], {%1,%2,%3,%4};" :: "r"(a), "r"(v0), "r"(v1), "r"(v2), "r"(v3));
}
__device__ __forceinline__ void sts64(uint32_t a, uint32_t v0, uint32_t v1) {
    asm volatile("st.shared.v2.b32 [%0], {%1,%2};" :: "r"(a), "r"(v0), "r"(v1));
}
__device__ __forceinline__ void mma_bf16(float* d, const uint32_t* a, const uint32_t* b) {
    asm volatile("mma.sync.aligned.m16n8k16.row.col.f32.bf16.bf16.f32 "
        "{%0,%1,%2,%3}, {%4,%5,%6,%7}, {%8,%9}, {%0,%1,%2,%3};"
        : "+f"(d[0]), "+f"(d[1]), "+f"(d[2]), "+f"(d[3])
        : "r"(a[0]), "r"(a[1]), "r"(a[2]), "r"(a[3]), "r"(b[0]), "r"(b[1]));
}
__device__ __forceinline__ uint32_t pack2(float a, float b) {   /* low = a, high = b */
    uint32_t r; asm("cvt.rn.bf16x2.f32 %0, %1, %2;" : "=r"(r) : "f"(b), "f"(a)); return r;
}
__device__ __forceinline__ void pack_pair(float a, float b, uint32_t& ph, uint32_t& pl) {
    ph = pack2(a, b);
    float ha = __uint_as_float(ph << 16);
    float hb = __uint_as_float(ph & 0xffff0000u);
    pl = pack2(a - ha, b - hb);
}

/* ---- prologue: split weights into bf16 hi/lo packed as mma B-fragments ---- */
__global__ void prep_w(const float* __restrict__ qkv_w, const float* __restrict__ proj_w) {
    int i = blockIdx.x * blockDim.x + threadIdx.x;
    if (i < 384 * 128) {
        int n0 = i >> 7, kl = i & 127;
        float f = qkv_w[i];
        __nv_bfloat16 h = __float2bfloat16_rn(f);
        __nv_bfloat16 lo = __float2bfloat16_rn(f - __bfloat162float(h));
        int np, nl;
        if (n0 >= 128 && n0 < 320) { np = 0; nl = n0 - 128; }
        else if (n0 < 128)         { np = 1; nl = n0; }
        else                       { np = 1; nl = n0 - 192; }
        int n16 = nl >> 4, nh8 = (nl >> 3) & 1, nin8 = nl & 7;
        int k16 = kl >> 4, km = kl & 15;
        int lane = nin8 * 4 + ((km & 7) >> 1);
        int r = nh8 * 2 + (km >> 3);
        int base = ((((np * 12 + n16) * 8 + k16) * 2 + 0) * 32 + lane) * 8 + r * 2 + (km & 1);
        g_qkvw[base]       = __bfloat16_as_ushort(h);
        g_qkvw[base + 256] = __bfloat16_as_ushort(lo);
    }
    if (i < 128 * 128) {
        int n = i >> 7, kl = i & 127;
        float f = proj_w[i];
        __nv_bfloat16 h = __float2bfloat16_rn(f);
        __nv_bfloat16 lo = __float2bfloat16_rn(f - __bfloat162float(h));
        int n16 = n >> 4, nh8 = (n >> 3) & 1, nin8 = n & 7;
        int k16 = kl >> 4, km = kl & 15;
        int lane = nin8 * 4 + ((km & 7) >> 1);
        int r = nh8 * 2 + (km >> 3);
        int base = (((n16 * 8 + k16) * 2 + 0) * 32 + lane) * 8 + r * 2 + (km & 1);
        g_projw[base]       = __bfloat16_as_ushort(h);
        g_projw[base + 256] = __bfloat16_as_ushort(lo);
    }
}

/* ---- main fused kernel: 256 threads, 2 CTAs/SM ---- */
__global__ __launch_bounds__(256, 2)
void win_attn_mma(const float* __restrict__ x,
                  const float* __restrict__ mask,
                  const float* __restrict__ qkv_b,
                  const float* __restrict__ proj_b,
                  const float* __restrict__ bt,
                  float* __restrict__ out,
                  int nW)
{
    extern __shared__ float sm[];
    uint16_t* u16b = (uint16_t*)sm;
    const int t = threadIdx.x;
    const int w = blockIdx.x;
    const long base = (long)w * (NT * CD);
    const int tn = t & 31, tm = t >> 5;   /* 8 warps */
    const uint32_t smb = smem_u32(sm);

    /* ---- stage x -> A split (swizzled, float2 + packed cvt); V pads; tables ---- */
    for (int i2 = t; i2 < NT * 64; i2 += 256) {
        int r = i2 >> 6, kp = (i2 & 63) * 2;
        float2 f = *(const float2*)&x[base + r * 128 + kp];
        int sw = ((kp >> 3) ^ (r & 7)) * 8 + (kp & 7);
        uint32_t ph, pl; pack_pair(f.x, f.y, ph, pl);
        *(uint32_t*)&u16b[r * 128 + sw]        = ph;
        *(uint32_t*)&u16b[8192 + r * 128 + sw] = pl;
    }
    /* zero V pad rows 49..63, all 8 blocks */
    for (int i = t; i < 1920; i += 256) {
        int blk = i / 240, rem = i - blk * 240;
        int rr = rem >> 4, dhp = rem & 15;
        *(uint32_t*)&u16b[U_V + (unsigned)blk * V_BLK + (unsigned)((49 + rr) * 40 + dhp * 2)] = 0u;
    }
    for (int idx = t; idx < 676; idx += 256) sm[F_BT + idx] = bt[idx];
    {
        uint8_t* rpw = (uint8_t*)sm + RPI_BYTE;
        for (int idx = t; idx < NT * NT; idx += 256) {
            int i = idx / NT, j = idx - i * NT;
            int yi = i / 7, xi = i - yi * 7;
            int yj = j / 7, xj = j - yj * 7;
            rpw[idx] = (uint8_t)((yi - yj + 6) * 13 + (xi - xj + 6));
        }
    }
    __syncthreads();

    const int l = tn;
    const int wm = tm & 1, wn = tm >> 1;
    const int a_r_off = l & 15;
    const int a_c_off = l >> 4;
    const float scale = 0.1767766952966369f;

    /* ======== QKV GEMM: two passes (np0=K+V01, np1=Q+V23), B via LDG.128 frags ======== */
    for (int np = 0; np < 2; np++) {
        float dacc[2][6][4];
#pragma unroll
        for (int a = 0; a < 2; a++)
#pragma unroll
            for (int b = 0; b < 6; b++)
#pragma unroll
                for (int c = 0; c < 4; c++) dacc[a][b][c] = 0.f;

#pragma unroll
        for (int kt = 0; kt < 8; kt++) {
            uint4 bh[3], bl[3];
#pragma unroll
            for (int p = 0; p < 3; p++) {
                unsigned off = (unsigned)(((((np * 12 + wn * 3 + p) * 8 + kt) * 2) * 32 + l) * 8);
                bh[p] = __ldg((const uint4*)&g_qkvw[off]);
                bl[p] = __ldg((const uint4*)&g_qkvw[off + 256]);
            }
            uint32_t ahi[2][4], alo[2][4];
#pragma unroll
            for (int mt = 0; mt < 2; mt++) {
                int r = wm * 32 + mt * 16 + a_r_off;
                int ch = kt * 2 + a_c_off;
                uint32_t ad = smb + (((unsigned)(r * 128) + (unsigned)((ch ^ (r & 7)) << 3)) << 1);
                ldsm4(ahi[mt], ad);
                ldsm4(alo[mt], ad + 16384u);
            }
#pragma unroll
            for (int mt = 0; mt < 2; mt++)
#pragma unroll
                for (int p = 0; p < 3; p++) {
                    uint32_t b0h[2] = { bh[p].x, bh[p].y };
                    uint32_t b1h[2] = { bh[p].z, bh[p].w };
                    uint32_t b0l[2] = { bl[p].x, bl[p].y };
                    uint32_t b1l[2] = { bl[p].z, bl[p].w };
                    mma_bf16(dacc[mt][p * 2],     ahi[mt], b0h);
                    mma_bf16(dacc[mt][p * 2],     ahi[mt], b0l);
                    mma_bf16(dacc[mt][p * 2],     alo[mt], b0h);
                    mma_bf16(dacc[mt][p * 2 + 1], ahi[mt], b1h);
                    mma_bf16(dacc[mt][p * 2 + 1], ahi[mt], b1l);
                    mma_bf16(dacc[mt][p * 2 + 1], alo[mt], b1h);
                }
        }
        if (np == 1) __syncthreads();   /* all x-A reads done before Q image overlays x */

        /* ---- epilogue: D-frags -> Q A-frag image / K B-frag image / V rows ---- */
#pragma unroll
        for (int mt = 0; mt < 2; mt++) {
            const int mtile = wm * 2 + mt;
#pragma unroll
            for (int p = 0; p < 3; p++) {
                int c0 = wn * 48 + p * 16;
                if (c0 < 128) {
                    float vv[2][4];
#pragma unroll
                    for (int e = 0; e < 2; e++) {
                        int cb = c0 + e * 8 + (l & 3) * 2;
                        int ob = np ? cb : 128 + cb;
                        float b0 = __ldg(qkv_b + ob), b1 = __ldg(qkv_b + ob + 1);
#pragma unroll
                        for (int rg = 0; rg < 4; rg++)
                            vv[e][rg] = dacc[mt][p * 2 + e][rg] + ((rg & 1) ? b1 : b0);
                    }
                    int k16g = wn * 3 + p;
                    int hh = k16g >> 1, kkk = k16g & 1;
                    if (np == 1) {   /* Q (scaled) -> A-frag image */
#pragma unroll
                        for (int e = 0; e < 2; e++)
#pragma unroll
                            for (int rg = 0; rg < 4; rg++) vv[e][rg] *= scale;
                        uint32_t h0, h1, h2, h3, lo0, lo1, lo2, lo3;
                        pack_pair(vv[0][0], vv[0][1], h0, lo0);
                        pack_pair(vv[0][2], vv[0][3], h1, lo1);
                        pack_pair(vv[1][0], vv[1][1], h2, lo2);
                        pack_pair(vv[1][2], vv[1][3], h3, lo3);
                        uint32_t ad = smb + (unsigned)(((hh * 4 + kkk) * 4 + mtile) * 512 + l * 16);
                        sts128(ad, h0, h1, h2, h3);
                        sts128(ad + 4096u, lo0, lo1, lo2, lo3);
                    } else {         /* K -> B-frag image */
                        uint32_t b00, b01, b10, b11, c00, c01, c10, c11;
                        pack_pair(vv[0][0], vv[0][1], b00, c00);
                        pack_pair(vv[1][0], vv[1][1], b01, c01);
                        pack_pair(vv[0][2], vv[0][3], b10, c10);
                        pack_pair(vv[1][2], vv[1][3], b11, c11);
                        uint32_t ad = smb + (U_KI << 1) +
                            (unsigned)(((hh * 4 + kkk) * 8 + mtile * 2) * 256 + l * 8);
                        sts64(ad, b00, b01);
                        sts64(ad + 256u, b10, b11);
                        sts64(ad + 4096u, c00, c01);
                        sts64(ad + 4096u + 256u, c10, c11);
                    }
                } else {             /* V rows (row-major, guarded) */
#pragma unroll
                    for (int e = 0; e < 2; e++) {
                        int nt = p * 2 + e;
                        int c = c0 + e * 8 + (l & 3) * 2;
                        int ob = np ? 192 + c : 128 + c;
                        float b0 = __ldg(qkv_b + ob), b1 = __ldg(qkv_b + ob + 1);
                        int hv = np * 2 + ((c - 128) >> 5);
                        int dh = (c - 128) & 31;
#pragma unroll
                        for (int rh = 0; rh < 2; rh++) {
                            int row = wm * 32 + mt * 16 + (l >> 2) + rh * 8;
                            if (row < NT) {
                                uint32_t ph, pl;
                                pack_pair(dacc[mt][nt][rh * 2] + b0,
                                          dacc[mt][nt][rh * 2 + 1] + b1, ph, pl);
                                uint32_t vb = U_V + (unsigned)(hv * 2) * V_BLK +
                                              (unsigned)(row * 40 + dh);
                                *(uint32_t*)&u16b[vb]         = ph;
                                *(uint32_t*)&u16b[vb + V_BLK] = pl;
                            }
                        }
                    }
                }
            }
        }
    }
    __syncthreads();

    /* ======== attention, register-resident; Q/K via frag-image LDS ======== */
    const float* mrow = mask + (long)(w % nW) * (NT * NT);
    const uint8_t* rp = (const uint8_t*)sm + RPI_BYTE;
    const int h = tm >> 1, half = tm & 1;
    const int cbase = (l & 3) * 2;

    float sacc[2][8][4];
#pragma unroll
    for (int s2 = 0; s2 < 2; s2++)
#pragma unroll
        for (int a = 0; a < 8; a++)
#pragma unroll
            for (int c = 0; c < 4; c++) sacc[s2][a][c] = 0.f;

#pragma unroll
    for (int kk = 0; kk < 2; kk++) {
        uint32_t aqh[2][4], aql[2][4];
#pragma unroll
        for (int s2 = 0; s2 < 2; s2++) {
            uint32_t qad = smb + (unsigned)((((h * 2) * 2 + kk) * 4 + (half * 2 + s2)) * 512 + l * 16);
            lds128(aqh[s2], qad);
            lds128(aql[s2], qad + 4096u);
        }
#pragma unroll
        for (int tg = 0; tg < 8; tg++) {
            uint32_t bh2[2], bl2[2];
            uint32_t kad = smb + (U_KI << 1) +
                (unsigned)((((h * 2) * 2 + kk) * 8 + tg) * 256 + l * 8);
            lds64(bh2, kad);
            lds64(bl2, kad + 4096u);
#pragma unroll
            for (int s2 = 0; s2 < 2; s2++) {
                mma_bf16(sacc[s2][tg], aqh[s2], bh2);
                mma_bf16(sacc[s2][tg], aqh[s2], bl2);
                mma_bf16(sacc[s2][tg], aql[s2], bh2);
            }
        }
    }

    /* ---- softmax in registers for both halves (+bias LDS +mask) ---- */
#pragma unroll
    for (int s2 = 0; s2 < 2; s2++) {
        const int r0 = (half * 2 + s2) * 16 + (l >> 2);
        const int r1 = r0 + 8;
        int r0c = (r0 < NT) ? r0 : (NT - 1);
        int r1c = (r1 < NT) ? r1 : (NT - 1);
        float m0 = -1e30f, m1 = -1e30f;
#pragma unroll
        for (int nt = 0; nt < 8; nt++)
#pragma unroll
            for (int j = 0; j < 2; j++) {
                int c = nt * 8 + cbase + j;
                if (c < NT) {
                    float bi0 = sm[F_BT + rp[r0c * NT + c] * 4 + h];
                    float bi1 = sm[F_BT + rp[r1c * NT + c] * 4 + h];
                    float mk0 = (r0 < NT) ? mrow[r0 * NT + c] : 0.f;
                    float mk1 = (r1 < NT) ? mrow[r1 * NT + c] : 0.f;
                    sacc[s2][nt][j]     += bi0 + mk0;
                    sacc[s2][nt][2 + j] += bi1 + mk1;
                } else {
                    sacc[s2][nt][j] = -1e30f;
                    sacc[s2][nt][2 + j] = -1e30f;
                }
                m0 = fmaxf(m0, sacc[s2][nt][j]);
                m1 = fmaxf(m1, sacc[s2][nt][2 + j]);
            }
        m0 = fmaxf(m0, __shfl_xor_sync(0xffffffffu, m0, 1));
        m0 = fmaxf(m0, __shfl_xor_sync(0xffffffffu, m0, 2));
        m1 = fmaxf(m1, __shfl_xor_sync(0xffffffffu, m1, 1));
        m1 = fmaxf(m1, __shfl_xor_sync(0xffffffffu, m1, 2));
        float s0 = 0.f, s1 = 0.f;
#pragma unroll
        for (int nt = 0; nt < 8; nt++)
#pragma unroll
            for (int j = 0; j < 2; j++) {
                float e0 = __expf(sacc[s2][nt][j] - m0);
                float e1 = __expf(sacc[s2][nt][2 + j] - m1);
                sacc[s2][nt][j] = e0; sacc[s2][nt][2 + j] = e1;
                s0 += e0; s1 += e1;
            }
        s0 += __shfl_xor_sync(0xffffffffu, s0, 1);
        s0 += __shfl_xor_sync(0xffffffffu, s0, 2);
        s1 += __shfl_xor_sync(0xffffffffu, s1, 1);
        s1 += __shfl_xor_sync(0xffffffffu, s1, 2);
        float i0 = 1.f / s0, i1 = 1.f / s1;
#pragma unroll
        for (int nt = 0; nt < 8; nt++)
#pragma unroll
            for (int j = 0; j < 2; j++) { sacc[s2][nt][j] *= i0; sacc[s2][nt][2 + j] *= i1; }
    }

    /* ---- PV for both halves: P packed in regs; V via ldmatrix.trans ---- */
    float oacc[2][4][4];
#pragma unroll
    for (int a = 0; a < 2; a++)
#pragma unroll
        for (int b = 0; b < 4; b++)
#pragma unroll
            for (int c = 0; c < 4; c++) oacc[a][b][c] = 0.f;

#pragma unroll
    for (int kt = 0; kt < 4; kt++) {
        uint32_t ah[2][4], al[2][4];
#pragma unroll
        for (int s2 = 0; s2 < 2; s2++) {
            pack_pair(sacc[s2][2 * kt][0],     sacc[s2][2 * kt][1],     ah[s2][0], al[s2][0]);
            pack_pair(sacc[s2][2 * kt][2],     sacc[s2][2 * kt][3],     ah[s2][1], al[s2][1]);
            pack_pair(sacc[s2][2 * kt + 1][0], sacc[s2][2 * kt + 1][1], ah[s2][2], al[s2][2]);
            pack_pair(sacc[s2][2 * kt + 1][2], sacc[s2][2 * kt + 1][3], ah[s2][3], al[s2][3]);
        }
#pragma unroll
        for (int g = 0; g < 2; g++) {
            uint32_t bh4[4], bl4[4];
            uint32_t vad = smb + ((U_V + (unsigned)(h * 2) * V_BLK +
                (unsigned)((kt * 16 + a_r_off) * 40 + g * 16 + a_c_off * 8)) << 1);
            ldsm4t(bh4, vad);
            ldsm4t(bl4, vad + (V_BLK << 1));
            uint32_t b0h[2] = { bh4[0], bh4[1] }, b1h[2] = { bh4[2], bh4[3] };
            uint32_t b0l[2] = { bl4[0], bl4[1] }, b1l[2] = { bl4[2], bl4[3] };
#pragma unroll
            for (int s2 = 0; s2 < 2; s2++) {
                mma_bf16(oacc[s2][g * 2],     ah[s2], b0h);
                mma_bf16(oacc[s2][g * 2],     ah[s2], b0l);
                mma_bf16(oacc[s2][g * 2],     al[s2], b0h);
                mma_bf16(oacc[s2][g * 2 + 1], ah[s2], b1h);
                mma_bf16(oacc[s2][g * 2 + 1], ah[s2], b1l);
                mma_bf16(oacc[s2][g * 2 + 1], al[s2], b1h);
            }
        }
    }
    __syncthreads();   /* all Q/K/V reads done; K image region about to be overwritten */

    /* ---- O fragments -> A-frag image (overlays K image) ---- */
#pragma unroll
    for (int s2 = 0; s2 < 2; s2++)
#pragma unroll
        for (int p2 = 0; p2 < 2; p2++) {
            uint32_t h0, h1, h2, h3, lo0, lo1, lo2, lo3;
            pack_pair(oacc[s2][2 * p2][0],     oacc[s2][2 * p2][1],     h0, lo0);
            pack_pair(oacc[s2][2 * p2][2],     oacc[s2][2 * p2][3],     h1, lo1);
            pack_pair(oacc[s2][2 * p2 + 1][0], oacc[s2][2 * p2 + 1][1], h2, lo2);
            pack_pair(oacc[s2][2 * p2 + 1][2], oacc[s2][2 * p2 + 1][3], h3, lo3);
            uint32_t ad = smb + (U_KI << 1) +
                (unsigned)(((h * 2 + p2) * 4 + (half * 2 + s2)) * 512 + l * 16);
            sts128(ad, h0, h1, h2, h3);
            sts128(ad + 16384u, lo0, lo1, lo2, lo3);
        }
    __syncthreads();

    /* ======== proj GEMM: A via frag-image LDS, B via LDG.128 frags ======== */
    float pacc[2][4][4];
#pragma unroll
    for (int a = 0; a < 2; a++)
#pragma unroll
        for (int b = 0; b < 4; b++)
#pragma unroll
            for (int c = 0; c < 4; c++) pacc[a][b][c] = 0.f;

#pragma unroll
    for (int kt = 0; kt < 8; kt++) {
        uint4 bh[2], bl[2];
#pragma unroll
        for (int p2 = 0; p2 < 2; p2++) {
            unsigned off = (unsigned)((((wn * 2 + p2) * 8 + kt) * 2 * 32 + l) * 8);
            bh[p2] = __ldg((const uint4*)&g_projw[off]);
            bl[p2] = __ldg((const uint4*)&g_projw[off + 256]);
        }
        uint32_t ahi[2][4], alo[2][4];
#pragma unroll
        for (int mt2 = 0; mt2 < 2; mt2++) {
            uint32_t ad = smb + (U_KI << 1) +
                (unsigned)((kt * 4 + wm * 2 + mt2) * 512 + l * 16);
            lds128(ahi[mt2], ad);
            lds128(alo[mt2], ad + 16384u);
        }
#pragma unroll
        for (int mt2 = 0; mt2 < 2; mt2++)
#pragma unroll
            for (int p2 = 0; p2 < 2; p2++) {
                uint32_t b0h[2] = { bh[p2].x, bh[p2].y };
                uint32_t b1h[2] = { bh[p2].z, bh[p2].w };
                uint32_t b0l[2] = { bl[p2].x, bl[p2].y };
                uint32_t b1l[2] = { bl[p2].z, bl[p2].w };
                mma_bf16(pacc[mt2][p2 * 2],     ahi[mt2], b0h);
                mma_bf16(pacc[mt2][p2 * 2],     ahi[mt2], b0l);
                mma_bf16(pacc[mt2][p2 * 2],     alo[mt2], b0h);
                mma_bf16(pacc[mt2][p2 * 2 + 1], ahi[mt2], b1h);
                mma_bf16(pacc[mt2][p2 * 2 + 1], ahi[mt2], b1l);
                mma_bf16(pacc[mt2][p2 * 2 + 1], alo[mt2], b1h);
            }
    }

    /* ---- epilogue: direct fragment stores (+bias) ---- */
#pragma unroll
    for (int mt2 = 0; mt2 < 2; mt2++)
#pragma unroll
        for (int nt = 0; nt < 4; nt++)
#pragma unroll
            for (int rh = 0; rh < 2; rh++) {
                int row = wm * 32 + mt2 * 16 + (l >> 2) + rh * 8;
                if (row < NT) {
                    int col = wn * 32 + nt * 8 + cbase;
                    float2 v;
                    v.x = pacc[mt2][nt][rh * 2]     + __ldg(proj_b + col);
                    v.y = pacc[mt2][nt][rh * 2 + 1] + __ldg(proj_b + col + 1);
                    *(float2*)&out[base + row * CD + col] = v;
                }
            }
}

extern "C" void kernel_launch(void* const* d_in, const int* in_sizes, int n_in,
                              void* d_out, int out_size) {
    const float* x      = (const float*)d_in[0];
    const float* mask   = (const float*)d_in[1];
    const float* qkv_w  = (const float*)d_in[2];
    const float* qkv_b  = (const float*)d_in[3];
    const float* proj_w = (const float*)d_in[4];
    const float* proj_b = (const float*)d_in[5];
    const float* bt     = (const float*)d_in[6];
    float* out = (float*)d_out;

    int B  = in_sizes[0] / (NT * CD);     /* 16384 */
    int nW = in_sizes[1] / (NT * NT);     /* 1024 */

    prep_w<<<96, 512>>>(qkv_w, proj_w);

    cudaFuncSetAttribute(win_attn_mma,
                         cudaFuncAttributeMaxDynamicSharedMemorySize, SMEM_BYTES);
    win_attn_mma<<<B, 256, SMEM_BYTES>>>(x, mask, qkv_b, proj_b, bt, out, nW);
}